// round 3
// baseline (speedup 1.0000x reference)
#include <cuda_runtime.h>

// Problem constants
#define BB 2
#define CC 1024
#define LL 2048
#define HH 16
#define HD 64
#define BCL (BB*CC*LL)               // 4,194,304 floats
#define NBH (BB*HH)                  // 32

// Scratch (device globals — runtime allocation is forbidden)
__device__ float g_K [BCL];
__device__ float g_Q [BCL];
__device__ float g_AO[BCL];
__device__ float g_Y [BCL];
__device__ float g_T [BCL];
__device__ float g_M [NBH*LL];       // per-row softmax max
__device__ float g_Zi[NBH*LL];       // per-row 1/sum

// ---------------------------------------------------------------------------
// conv1x1: Out[b,o,l] = sum_c W[o,c]*X[b,c,l] + bias[o]  (+A1 +A2, relu opt)
// 128(o) x 128(l) block tile, K-tile 8, 256 threads, 8x8 per thread,
// double-buffered shared memory with register prefetch.
// ---------------------------------------------------------------------------
template<bool RELU, int NADD>
__global__ __launch_bounds__(256, 2)
void conv1x1_kernel(const float* __restrict__ W, const float* __restrict__ bias,
                    const float* __restrict__ X, float* __restrict__ Out,
                    const float* __restrict__ A1, const float* __restrict__ A2)
{
    const int b  = blockIdx.z;
    const int o0 = blockIdx.y * 128;
    const int l0 = blockIdx.x * 128;
    const float* Xb = X + (size_t)b * CC * LL;
    float* Ob = Out + (size_t)b * CC * LL;

    __shared__ float sW[2][8][128];   // [buf][c][o]
    __shared__ float sX[2][8][128];   // [buf][c][l]

    const int tid = threadIdx.x;
    const int tx = tid & 15;          // l group
    const int ty = tid >> 4;          // o group
    const int woo = tid & 127;        // W loader: o index
    const int wc4 = (tid >> 7) * 4;   // W loader: c base (0 or 4)
    const int xcc = tid >> 5;         // X loader: c index (0..7)
    const int xl4 = (tid & 31) * 4;   // X loader: l base

    float acc[8][8] = {};

    // prologue: tile 0
    {
        float4 wv = *(const float4*)&W[(size_t)(o0 + woo) * CC + wc4];
        float4 xv = *(const float4*)&Xb[(size_t)xcc * LL + l0 + xl4];
        sW[0][wc4 + 0][woo] = wv.x;
        sW[0][wc4 + 1][woo] = wv.y;
        sW[0][wc4 + 2][woo] = wv.z;
        sW[0][wc4 + 3][woo] = wv.w;
        *(float4*)&sX[0][xcc][xl4] = xv;
    }
    __syncthreads();

    int buf = 0;
    for (int c0 = 0; c0 < CC; c0 += 8) {
        float4 wn, xn;
        const bool more = (c0 + 8 < CC);
        if (more) {
            wn = *(const float4*)&W[(size_t)(o0 + woo) * CC + c0 + 8 + wc4];
            xn = *(const float4*)&Xb[(size_t)(c0 + 8 + xcc) * LL + l0 + xl4];
        }

        #pragma unroll
        for (int k = 0; k < 8; k++) {
            float4 a0 = *(float4*)&sW[buf][k][ty * 4];
            float4 a1 = *(float4*)&sW[buf][k][64 + ty * 4];
            float4 b0 = *(float4*)&sX[buf][k][tx * 4];
            float4 b1 = *(float4*)&sX[buf][k][64 + tx * 4];
            float aa[8] = {a0.x, a0.y, a0.z, a0.w, a1.x, a1.y, a1.z, a1.w};
            float bb[8] = {b0.x, b0.y, b0.z, b0.w, b1.x, b1.y, b1.z, b1.w};
            #pragma unroll
            for (int i = 0; i < 8; i++)
                #pragma unroll
                for (int j = 0; j < 8; j++)
                    acc[i][j] = fmaf(aa[i], bb[j], acc[i][j]);
        }

        if (more) {
            sW[buf ^ 1][wc4 + 0][woo] = wn.x;
            sW[buf ^ 1][wc4 + 1][woo] = wn.y;
            sW[buf ^ 1][wc4 + 2][woo] = wn.z;
            sW[buf ^ 1][wc4 + 3][woo] = wn.w;
            *(float4*)&sX[buf ^ 1][xcc][xl4] = xn;
        }
        __syncthreads();
        buf ^= 1;
    }

    const size_t boff = (size_t)b * CC * LL;
    #pragma unroll
    for (int ih = 0; ih < 2; ih++)
    #pragma unroll
    for (int ii = 0; ii < 4; ii++) {
        const int o = o0 + ih * 64 + ty * 4 + ii;
        const float bvv = bias[o];
        #pragma unroll
        for (int jh = 0; jh < 2; jh++) {
            const int l = l0 + jh * 64 + tx * 4;
            float4 v;
            v.x = acc[ih * 4 + ii][jh * 4 + 0] + bvv;
            v.y = acc[ih * 4 + ii][jh * 4 + 1] + bvv;
            v.z = acc[ih * 4 + ii][jh * 4 + 2] + bvv;
            v.w = acc[ih * 4 + ii][jh * 4 + 3] + bvv;
            if (RELU) {
                v.x = fmaxf(v.x, 0.f); v.y = fmaxf(v.y, 0.f);
                v.z = fmaxf(v.z, 0.f); v.w = fmaxf(v.w, 0.f);
            }
            const size_t idx = boff + (size_t)o * LL + l;
            if (NADD >= 1) {
                float4 a = *(const float4*)&A1[idx];
                v.x += a.x; v.y += a.y; v.z += a.z; v.w += a.w;
            }
            if (NADD >= 2) {
                float4 a = *(const float4*)&A2[idx];
                v.x += a.x; v.y += a.y; v.z += a.z; v.w += a.w;
            }
            *(float4*)&Ob[(size_t)o * LL + l] = v;
        }
    }
}

// ---------------------------------------------------------------------------
// Pass 1: per-row softmax stats. For each (bh, l) compute
//   M[l] = max_m S[l,m],  Zi[l] = 1/sum_m exp(S[l,m]-M[l]),
// where S[l,m] = (1/1024) * sum_c K[bh,c,l]*Q[bh,c,m]  (streamed, never stored)
// Block = 64 l-rows for one bh; loop m in tiles of 64.
// ---------------------------------------------------------------------------
__global__ __launch_bounds__(256)
void rowstats_kernel(const float* __restrict__ K, const float* __restrict__ Q,
                     float* __restrict__ M, float* __restrict__ Zi)
{
    const int bh = blockIdx.y;
    const int b = bh >> 4, h = bh & 15;
    const int l0 = blockIdx.x * 64;
    const size_t hoff = (size_t)b * CC * LL + (size_t)h * HD * LL;
    const float* Kb = K + hoff;
    const float* Qb = Q + hoff;

    __shared__ float sK[64][64];   // [c][l]
    __shared__ float sQ[64][64];   // [c][m]

    const int tid = threadIdx.x;
    const int tx = tid & 15, ty = tid >> 4;
    const int lc  = tid >> 4;          // loader row group 0..15
    const int lm4 = (tid & 15) * 4;    // loader col base

    // load K tile once
    #pragma unroll
    for (int p = 0; p < 4; p++)
        *(float4*)&sK[lc + p * 16][lm4] =
            *(const float4*)&Kb[(size_t)(lc + p * 16) * LL + l0 + lm4];

    float mr[4], sr[4];
    #pragma unroll
    for (int i = 0; i < 4; i++) { mr[i] = -1e30f; sr[i] = 0.0f; }

    const float scale = 1.0f / 1024.0f;

    for (int m0 = 0; m0 < LL; m0 += 64) {
        __syncthreads();
        #pragma unroll
        for (int p = 0; p < 4; p++)
            *(float4*)&sQ[lc + p * 16][lm4] =
                *(const float4*)&Qb[(size_t)(lc + p * 16) * LL + m0 + lm4];
        __syncthreads();

        float acc[4][4] = {};
        #pragma unroll 16
        for (int k = 0; k < 64; k++) {
            float4 a  = *(float4*)&sK[k][ty * 4];
            float4 bq = *(float4*)&sQ[k][tx * 4];
            float aa[4] = {a.x, a.y, a.z, a.w};
            float bb[4] = {bq.x, bq.y, bq.z, bq.w};
            #pragma unroll
            for (int i = 0; i < 4; i++)
                #pragma unroll
                for (int j = 0; j < 4; j++)
                    acc[i][j] = fmaf(aa[i], bb[j], acc[i][j]);
        }

        #pragma unroll
        for (int i = 0; i < 4; i++) {
            float v0 = acc[i][0] * scale, v1 = acc[i][1] * scale;
            float v2 = acc[i][2] * scale, v3 = acc[i][3] * scale;
            float tmax = fmaxf(fmaxf(v0, v1), fmaxf(v2, v3));
            float tsum = __expf(v0 - tmax) + __expf(v1 - tmax)
                       + __expf(v2 - tmax) + __expf(v3 - tmax);
            float nm = fmaxf(mr[i], tmax);
            sr[i] = sr[i] * __expf(mr[i] - nm) + tsum * __expf(tmax - nm);
            mr[i] = nm;
        }
    }

    // reduce across tx lanes (bits 0..3 of lane id)
    #pragma unroll
    for (int i = 0; i < 4; i++) {
        float m = mr[i], s = sr[i];
        #pragma unroll
        for (int off = 1; off < 16; off <<= 1) {
            float om = __shfl_xor_sync(0xffffffffu, m, off);
            float os = __shfl_xor_sync(0xffffffffu, s, off);
            float nm = fmaxf(m, om);
            s = s * __expf(m - nm) + os * __expf(om - nm);
            m = nm;
        }
        if (tx == 0) {
            const int l = l0 + ty * 4 + i;
            M [(size_t)bh * LL + l] = m;
            Zi[(size_t)bh * LL + l] = 1.0f / s;
        }
    }
}

// ---------------------------------------------------------------------------
// Pass 2: fused scores-recompute + softmax-apply + AV GEMM.
// Block = (bh, m-tile of 64). Loops l in tiles of 64:
//   S_tile = K_tile^T Q_tile /1024 ; P = exp(S - M[l])*Zi[l] (smem)
//   O[c, m] += X[c, l_tile] @ P
// ---------------------------------------------------------------------------
#define P_PITCH 68

__global__ __launch_bounds__(256, 2)
void av_fused_kernel(const float* __restrict__ X, const float* __restrict__ K,
                     const float* __restrict__ Q, const float* __restrict__ M,
                     const float* __restrict__ Zi, float* __restrict__ O)
{
    extern __shared__ float sm[];
    float* sQ  = sm;              // [64][64]  [c][m]
    float* sK  = sQ + 64 * 64;    // [64][64]  [c][l]
    float* sXt = sK + 64 * 64;    // [64][64]  [l][c]  (X transposed)
    float* sP  = sXt + 64 * 64;   // [64][P_PITCH]  [l][m]

    const int bh = blockIdx.y;
    const int b = bh >> 4, h = bh & 15;
    const int m0 = blockIdx.x * 64;
    const size_t hoff = (size_t)b * CC * LL + (size_t)h * HD * LL;
    const float* Xb = X + hoff;
    const float* Kb = K + hoff;
    const float* Qb = Q + hoff;
    const float* Mb = M  + (size_t)bh * LL;
    const float* Zb = Zi + (size_t)bh * LL;

    const int tid = threadIdx.x;
    const int tx = tid & 15, ty = tid >> 4;
    const int lc  = tid >> 4;
    const int lm4 = (tid & 15) * 4;
    const int xc = tid & 63;       // Xt loader: c
    const int xg = tid >> 6;       // Xt loader: l group 0..3

    // load Q tile once
    #pragma unroll
    for (int p = 0; p < 4; p++)
        *(float4*)&sQ[(lc + p * 16) * 64 + lm4] =
            *(const float4*)&Qb[(size_t)(lc + p * 16) * LL + m0 + lm4];

    float acc2[4][4] = {};
    const float scale = 1.0f / 1024.0f;

    for (int l0 = 0; l0 < LL; l0 += 64) {
        __syncthreads();
        // K tile [c][l]
        #pragma unroll
        for (int p = 0; p < 4; p++)
            *(float4*)&sK[(lc + p * 16) * 64 + lm4] =
                *(const float4*)&Kb[(size_t)(lc + p * 16) * LL + l0 + lm4];
        // X tile transposed -> sXt[l][c]
        #pragma unroll
        for (int p = 0; p < 4; p++) {
            const int l4 = xg * 4 + p * 16;
            float4 v = *(const float4*)&Xb[(size_t)xc * LL + l0 + l4];
            sXt[(l4 + 0) * 64 + xc] = v.x;
            sXt[(l4 + 1) * 64 + xc] = v.y;
            sXt[(l4 + 2) * 64 + xc] = v.z;
            sXt[(l4 + 3) * 64 + xc] = v.w;
        }
        __syncthreads();

        // GEMM1: scores tile, rows l=ty*4+i, cols m=tx*4+j
        float acc1[4][4] = {};
        #pragma unroll 16
        for (int k = 0; k < 64; k++) {
            float4 a  = *(float4*)&sK[k * 64 + ty * 4];
            float4 bq = *(float4*)&sQ[k * 64 + tx * 4];
            float aa[4] = {a.x, a.y, a.z, a.w};
            float bb[4] = {bq.x, bq.y, bq.z, bq.w};
            #pragma unroll
            for (int i = 0; i < 4; i++)
                #pragma unroll
                for (int j = 0; j < 4; j++)
                    acc1[i][j] = fmaf(aa[i], bb[j], acc1[i][j]);
        }

        // softmax-apply -> P
        #pragma unroll
        for (int i = 0; i < 4; i++) {
            const int l = l0 + ty * 4 + i;
            const float mrow = Mb[l];
            const float zrow = Zb[l];
            float4 pv;
            pv.x = __expf(fmaf(acc1[i][0], scale, -mrow)) * zrow;
            pv.y = __expf(fmaf(acc1[i][1], scale, -mrow)) * zrow;
            pv.z = __expf(fmaf(acc1[i][2], scale, -mrow)) * zrow;
            pv.w = __expf(fmaf(acc1[i][3], scale, -mrow)) * zrow;
            *(float4*)&sP[(ty * 4 + i) * P_PITCH + tx * 4] = pv;
        }
        __syncthreads();

        // GEMM2: O[c][m] += X[c][l] * P[l][m], rows c=ty*4+i
        #pragma unroll 16
        for (int k = 0; k < 64; k++) {
            float4 a  = *(float4*)&sXt[k * 64 + ty * 4];
            float4 bp = *(float4*)&sP[k * P_PITCH + tx * 4];
            float aa[4] = {a.x, a.y, a.z, a.w};
            float bb[4] = {bp.x, bp.y, bp.z, bp.w};
            #pragma unroll
            for (int i = 0; i < 4; i++)
                #pragma unroll
                for (int j = 0; j < 4; j++)
                    acc2[i][j] = fmaf(aa[i], bb[j], acc2[i][j]);
        }
    }

    float* Ob = O + hoff;
    #pragma unroll
    for (int i = 0; i < 4; i++) {
        const int c = ty * 4 + i;
        float4 v;
        v.x = acc2[i][0]; v.y = acc2[i][1]; v.z = acc2[i][2]; v.w = acc2[i][3];
        *(float4*)&Ob[(size_t)c * LL + m0 + tx * 4] = v;
    }
}

#define AV_SMEM_BYTES ((3 * 64 * 64 + 64 * P_PITCH) * 4)

// ---------------------------------------------------------------------------
extern "C" void kernel_launch(void* const* d_in, const int* in_sizes, int n_in,
                              void* d_out, int out_size)
{
    const float* x   = (const float*)d_in[0];
    const float* kw  = (const float*)d_in[1];
    const float* kb  = (const float*)d_in[2];
    const float* qw  = (const float*)d_in[3];
    const float* qb  = (const float*)d_in[4];
    const float* pw  = (const float*)d_in[5];
    const float* pb  = (const float*)d_in[6];
    const float* c1w = (const float*)d_in[7];
    const float* c1b = (const float*)d_in[8];
    const float* c2w = (const float*)d_in[9];
    const float* c2b = (const float*)d_in[10];
    float* out = (float*)d_out;

    float *gK, *gQ, *gAO, *gY, *gT, *gM, *gZi;
    cudaGetSymbolAddress((void**)&gK,  g_K);
    cudaGetSymbolAddress((void**)&gQ,  g_Q);
    cudaGetSymbolAddress((void**)&gAO, g_AO);
    cudaGetSymbolAddress((void**)&gY,  g_Y);
    cudaGetSymbolAddress((void**)&gT,  g_T);
    cudaGetSymbolAddress((void**)&gM,  g_M);
    cudaGetSymbolAddress((void**)&gZi, g_Zi);

    static bool attr_done = false;
    if (!attr_done) {
        cudaFuncSetAttribute(av_fused_kernel,
                             cudaFuncAttributeMaxDynamicSharedMemorySize,
                             AV_SMEM_BYTES);
        attr_done = true;
    }

    dim3 cgrid(LL / 128, CC / 128, BB);   // (16,8,2)
    dim3 cblk(256);

    // K and Q projections
    conv1x1_kernel<false, 0><<<cgrid, cblk>>>(kw, kb, x, gK, nullptr, nullptr);
    conv1x1_kernel<false, 0><<<cgrid, cblk>>>(qw, qb, x, gQ, nullptr, nullptr);

    // fused attention: stats pass + recompute/apply/AV pass
    rowstats_kernel<<<dim3(LL / 64, NBH), 256>>>(gK, gQ, gM, gZi);
    av_fused_kernel<<<dim3(LL / 64, NBH), 256, AV_SMEM_BYTES>>>(x, gK, gQ, gM, gZi, gAO);

    // y = pconv(attn_out) + x
    conv1x1_kernel<false, 1><<<cgrid, cblk>>>(pw, pb, gAO, gY, x, nullptr);
    // t = relu(c1(y))
    conv1x1_kernel<true, 0><<<cgrid, cblk>>>(c1w, c1b, gY, gT, nullptr, nullptr);
    // out = c2(t) + y + x
    conv1x1_kernel<false, 2><<<cgrid, cblk>>>(c2w, c2b, gT, out, gY, x);
}

// round 4
// speedup vs baseline: 2.0706x; 2.0706x over previous
#include <cuda_runtime.h>

// Problem constants
#define BB 2
#define CC 1024
#define LL 2048
#define HH 16
#define HD 64
#define BCL (BB*CC*LL)               // 4,194,304 floats
#define NBH (BB*HH)                  // 32
#define SROWS ((size_t)NBH * LL)     // 65536
#define SELEMS (SROWS * LL)          // 134,217,728 floats (512 MB)

// Scratch (device globals — runtime allocation is forbidden)
__device__ float g_K [BCL];
__device__ float g_Q [BCL];
__device__ float g_S [SELEMS];
__device__ float g_AO[BCL];
__device__ float g_Y [BCL];
__device__ float g_T [BCL];

// ---------------------------------------------------------------------------
// Packed f32x2 helpers (Blackwell FFMA2 — only reachable via PTX)
// ---------------------------------------------------------------------------
typedef unsigned long long u64;

__device__ __forceinline__ u64 pack2(float x, float y) {
    u64 r; asm("mov.b64 %0, {%1, %2};" : "=l"(r) : "f"(x), "f"(y)); return r;
}
__device__ __forceinline__ float2 unpack2(u64 v) {
    float2 r; asm("mov.b64 {%0, %1}, %2;" : "=f"(r.x), "=f"(r.y) : "l"(v)); return r;
}
__device__ __forceinline__ void ffma2(u64& d, u64 a, u64 b) {
    asm("fma.rn.f32x2 %0, %1, %2, %0;" : "+l"(d) : "l"(a), "l"(b));
}

// 8x8 packed FMA micro-tile: acc2[8][4] (each u64 = 2 adjacent cols)
__device__ __forceinline__ void mma8x8(u64 acc2[8][4],
                                       float4 a0, float4 a1,
                                       float4 b0, float4 b1)
{
    u64 bp[4];
    bp[0] = pack2(b0.x, b0.y); bp[1] = pack2(b0.z, b0.w);
    bp[2] = pack2(b1.x, b1.y); bp[3] = pack2(b1.z, b1.w);
    float aa[8] = {a0.x, a0.y, a0.z, a0.w, a1.x, a1.y, a1.z, a1.w};
    #pragma unroll
    for (int i = 0; i < 8; i++) {
        u64 ad = pack2(aa[i], aa[i]);
        #pragma unroll
        for (int jp = 0; jp < 4; jp++)
            ffma2(acc2[i][jp], ad, bp[jp]);
    }
}

// ---------------------------------------------------------------------------
// conv1x1: Out[b,o,l] = sum_c W[o,c]*X[b,c,l] + bias[o]  (+A1 +A2, relu opt)
// 128(o) x 128(l) block tile, K-tile 8, 256 threads, 8x8/thread, FFMA2,
// double-buffered shared memory with register prefetch.
// ---------------------------------------------------------------------------
template<bool RELU, int NADD>
__global__ __launch_bounds__(256, 2)
void conv1x1_kernel(const float* __restrict__ W, const float* __restrict__ bias,
                    const float* __restrict__ X, float* __restrict__ Out,
                    const float* __restrict__ A1, const float* __restrict__ A2)
{
    const int b  = blockIdx.z;
    const int o0 = blockIdx.y * 128;
    const int l0 = blockIdx.x * 128;
    const float* Xb = X + (size_t)b * CC * LL;
    float* Ob = Out + (size_t)b * CC * LL;

    __shared__ float sW[2][8][128];   // [buf][c][o]
    __shared__ float sX[2][8][128];   // [buf][c][l]

    const int tid = threadIdx.x;
    const int tx = tid & 15;
    const int ty = tid >> 4;
    const int woo = tid & 127;        // W loader: o index
    const int wc4 = (tid >> 7) * 4;   // W loader: c base (0 or 4)
    const int xcc = tid >> 5;         // X loader: c index (0..7)
    const int xl4 = (tid & 31) * 4;   // X loader: l base

    u64 acc2[8][4];
    #pragma unroll
    for (int i = 0; i < 8; i++)
        #pragma unroll
        for (int j = 0; j < 4; j++) acc2[i][j] = 0ull;

    // prologue: tile 0
    {
        float4 wv = *(const float4*)&W[(size_t)(o0 + woo) * CC + wc4];
        float4 xv = *(const float4*)&Xb[(size_t)xcc * LL + l0 + xl4];
        sW[0][wc4 + 0][woo] = wv.x;
        sW[0][wc4 + 1][woo] = wv.y;
        sW[0][wc4 + 2][woo] = wv.z;
        sW[0][wc4 + 3][woo] = wv.w;
        *(float4*)&sX[0][xcc][xl4] = xv;
    }
    __syncthreads();

    int buf = 0;
    for (int c0 = 0; c0 < CC; c0 += 8) {
        float4 wn, xn;
        const bool more = (c0 + 8 < CC);
        if (more) {
            wn = *(const float4*)&W[(size_t)(o0 + woo) * CC + c0 + 8 + wc4];
            xn = *(const float4*)&Xb[(size_t)(c0 + 8 + xcc) * LL + l0 + xl4];
        }

        #pragma unroll
        for (int k = 0; k < 8; k++) {
            float4 a0 = *(float4*)&sW[buf][k][ty * 4];
            float4 a1 = *(float4*)&sW[buf][k][64 + ty * 4];
            float4 b0 = *(float4*)&sX[buf][k][tx * 4];
            float4 b1 = *(float4*)&sX[buf][k][64 + tx * 4];
            mma8x8(acc2, a0, a1, b0, b1);
        }

        if (more) {
            sW[buf ^ 1][wc4 + 0][woo] = wn.x;
            sW[buf ^ 1][wc4 + 1][woo] = wn.y;
            sW[buf ^ 1][wc4 + 2][woo] = wn.z;
            sW[buf ^ 1][wc4 + 3][woo] = wn.w;
            *(float4*)&sX[buf ^ 1][xcc][xl4] = xn;
        }
        __syncthreads();
        buf ^= 1;
    }

    const size_t boff = (size_t)b * CC * LL;
    #pragma unroll
    for (int i = 0; i < 8; i++) {
        const int o = o0 + (i >> 2) * 64 + ty * 4 + (i & 3);
        const float bvv = bias[o];
        #pragma unroll
        for (int jh = 0; jh < 2; jh++) {
            const int l = l0 + jh * 64 + tx * 4;
            float2 p0 = unpack2(acc2[i][jh * 2 + 0]);
            float2 p1 = unpack2(acc2[i][jh * 2 + 1]);
            float4 v;
            v.x = p0.x + bvv; v.y = p0.y + bvv;
            v.z = p1.x + bvv; v.w = p1.y + bvv;
            if (RELU) {
                v.x = fmaxf(v.x, 0.f); v.y = fmaxf(v.y, 0.f);
                v.z = fmaxf(v.z, 0.f); v.w = fmaxf(v.w, 0.f);
            }
            const size_t idx = boff + (size_t)o * LL + l;
            if (NADD >= 1) {
                float4 a = *(const float4*)&A1[idx];
                v.x += a.x; v.y += a.y; v.z += a.z; v.w += a.w;
            }
            if (NADD >= 2) {
                float4 a = *(const float4*)&A2[idx];
                v.x += a.x; v.y += a.y; v.z += a.z; v.w += a.w;
            }
            *(float4*)&Ob[(size_t)o * LL + l] = v;
        }
    }
}

// ---------------------------------------------------------------------------
// scores: S[bh,l,m] = (1/1024) * sum_{c<64} K[bh,c,l] * Q[bh,c,m]
// 128x128 output tile, K=64 loaded once (no k-loop over gmem), 256 threads,
// 8x8/thread with FFMA2. Dynamic smem: 2 * 64*128 floats = 64 KB.
// ---------------------------------------------------------------------------
__global__ __launch_bounds__(256)
void scores_kernel(const float* __restrict__ K, const float* __restrict__ Q,
                   float* __restrict__ S)
{
    extern __shared__ float sm[];
    float* sK = sm;               // [64][128]  [c][l]
    float* sQ = sm + 64 * 128;    // [64][128]  [c][m]

    const int bh = blockIdx.z;
    const int b = bh >> 4, h = bh & 15;
    const int l0 = blockIdx.y * 128;
    const int m0 = blockIdx.x * 128;

    const size_t hoff = (size_t)b * CC * LL + (size_t)h * HD * LL;
    const float* Kb = K + hoff;
    const float* Qb = Q + hoff;
    float* Sb = S + (size_t)bh * LL * LL;

    const int tid = threadIdx.x;
    const int tx = tid & 15, ty = tid >> 4;
    const int lr  = tid >> 5;          // loader row base (0..7)
    const int lc4 = (tid & 31) * 4;    // loader col base

    #pragma unroll
    for (int p = 0; p < 8; p++) {
        const int c = lr + p * 8;
        *(float4*)&sK[c * 128 + lc4] = *(const float4*)&Kb[(size_t)c * LL + l0 + lc4];
        *(float4*)&sQ[c * 128 + lc4] = *(const float4*)&Qb[(size_t)c * LL + m0 + lc4];
    }
    __syncthreads();

    u64 acc2[8][4];
    #pragma unroll
    for (int i = 0; i < 8; i++)
        #pragma unroll
        for (int j = 0; j < 4; j++) acc2[i][j] = 0ull;

    #pragma unroll 4
    for (int k = 0; k < 64; k++) {
        float4 a0 = *(float4*)&sK[k * 128 + ty * 4];
        float4 a1 = *(float4*)&sK[k * 128 + 64 + ty * 4];
        float4 b0 = *(float4*)&sQ[k * 128 + tx * 4];
        float4 b1 = *(float4*)&sQ[k * 128 + 64 + tx * 4];
        mma8x8(acc2, a0, a1, b0, b1);
    }

    const float scale = 1.0f / 1024.0f;   // softmax(scores / (L/2))
    #pragma unroll
    for (int i = 0; i < 8; i++) {
        const int l = l0 + (i >> 2) * 64 + ty * 4 + (i & 3);
        #pragma unroll
        for (int jh = 0; jh < 2; jh++) {
            const int m = m0 + jh * 64 + tx * 4;
            float2 p0 = unpack2(acc2[i][jh * 2 + 0]);
            float2 p1 = unpack2(acc2[i][jh * 2 + 1]);
            float4 v;
            v.x = p0.x * scale; v.y = p0.y * scale;
            v.z = p1.x * scale; v.w = p1.y * scale;
            *(float4*)&Sb[(size_t)l * LL + m] = v;
        }
    }
}
#define SCORES_SMEM_BYTES (2 * 64 * 128 * 4)

// ---------------------------------------------------------------------------
// softmax over last axis (2048), one block (256 thr) per row, in place
// ---------------------------------------------------------------------------
__device__ __forceinline__ float warp_rmax(float v) {
    #pragma unroll
    for (int o = 16; o > 0; o >>= 1) v = fmaxf(v, __shfl_xor_sync(0xffffffffu, v, o));
    return v;
}
__device__ __forceinline__ float warp_rsum(float v) {
    #pragma unroll
    for (int o = 16; o > 0; o >>= 1) v += __shfl_xor_sync(0xffffffffu, v, o);
    return v;
}

__global__ __launch_bounds__(256)
void softmax_kernel(float* __restrict__ S)
{
    const size_t row = blockIdx.x;
    float* p = S + row * LL;
    const int tid = threadIdx.x;
    const int lane = tid & 31, wid = tid >> 5;

    float4 v0 = reinterpret_cast<float4*>(p)[tid];
    float4 v1 = reinterpret_cast<float4*>(p)[tid + 256];

    float m = fmaxf(fmaxf(fmaxf(v0.x, v0.y), fmaxf(v0.z, v0.w)),
                    fmaxf(fmaxf(v1.x, v1.y), fmaxf(v1.z, v1.w)));

    __shared__ float sred[8];
    __shared__ float sbroad;

    m = warp_rmax(m);
    if (lane == 0) sred[wid] = m;
    __syncthreads();
    if (tid == 0) {
        float t = sred[0];
        #pragma unroll
        for (int i = 1; i < 8; i++) t = fmaxf(t, sred[i]);
        sbroad = t;
    }
    __syncthreads();
    const float mx = sbroad;
    __syncthreads();

    v0.x = __expf(v0.x - mx); v0.y = __expf(v0.y - mx);
    v0.z = __expf(v0.z - mx); v0.w = __expf(v0.w - mx);
    v1.x = __expf(v1.x - mx); v1.y = __expf(v1.y - mx);
    v1.z = __expf(v1.z - mx); v1.w = __expf(v1.w - mx);

    float s = (v0.x + v0.y + v0.z + v0.w) + (v1.x + v1.y + v1.z + v1.w);
    s = warp_rsum(s);
    if (lane == 0) sred[wid] = s;
    __syncthreads();
    if (tid == 0) {
        float t = 0.0f;
        #pragma unroll
        for (int i = 0; i < 8; i++) t += sred[i];
        sbroad = t;
    }
    __syncthreads();
    const float inv = 1.0f / sbroad;

    v0.x *= inv; v0.y *= inv; v0.z *= inv; v0.w *= inv;
    v1.x *= inv; v1.y *= inv; v1.z *= inv; v1.w *= inv;
    reinterpret_cast<float4*>(p)[tid]       = v0;
    reinterpret_cast<float4*>(p)[tid + 256] = v1;
}

// ---------------------------------------------------------------------------
// AV: O[bh,c,m] = sum_l X[bh,c,l] * A[bh,l,m]   (c<64 per head)
// 64(c) x 128(m) block tile, 128 threads, 8x8/thread with FFMA2.
// Dynamic smem: sXt[64][68] + sP[64][128] = 50,176 B.
// ---------------------------------------------------------------------------
#define XT_PITCH 68

__global__ __launch_bounds__(128)
void av_kernel(const float* __restrict__ X, const float* __restrict__ A,
               float* __restrict__ O)
{
    extern __shared__ float sm[];
    float* sXt = sm;                    // [64 l][68]  (X transposed: [l][c])
    float* sP  = sm + 64 * XT_PITCH;    // [64 l][128 m]

    const int bh = blockIdx.y;
    const int b = bh >> 4, h = bh & 15;
    const int m0 = blockIdx.x * 128;

    const size_t hoff = (size_t)b * CC * LL + (size_t)h * HD * LL;
    const float* Xb = X + hoff;
    const float* Ab = A + (size_t)bh * LL * LL;
    float* Ob = O + hoff;

    const int tid = threadIdx.x;
    const int tx = tid & 15, ty = tid >> 4;   // ty 0..7
    const int xc = tid & 63;                  // Xt loader: c
    const int xg = tid >> 6;                  // Xt loader: l group (0..1)
    const int pr = tid >> 5;                  // P loader: row base (0..3)
    const int pc4 = (tid & 31) * 4;           // P loader: col base

    u64 acc2[8][4];
    #pragma unroll
    for (int i = 0; i < 8; i++)
        #pragma unroll
        for (int j = 0; j < 4; j++) acc2[i][j] = 0ull;

    for (int l0 = 0; l0 < LL; l0 += 64) {
        __syncthreads();
        // X tile transposed: sXt[l][c]
        #pragma unroll
        for (int p = 0; p < 8; p++) {
            const int l4 = (xg + p * 2) * 4;
            float4 v = *(const float4*)&Xb[(size_t)xc * LL + l0 + l4];
            sXt[(l4 + 0) * XT_PITCH + xc] = v.x;
            sXt[(l4 + 1) * XT_PITCH + xc] = v.y;
            sXt[(l4 + 2) * XT_PITCH + xc] = v.z;
            sXt[(l4 + 3) * XT_PITCH + xc] = v.w;
        }
        // P tile: sP[l][m]
        #pragma unroll
        for (int p = 0; p < 16; p++) {
            const int r = pr + p * 4;
            *(float4*)&sP[r * 128 + pc4] =
                *(const float4*)&Ab[(size_t)(l0 + r) * LL + m0 + pc4];
        }
        __syncthreads();

        #pragma unroll 4
        for (int k = 0; k < 64; k++) {
            float4 a0 = *(float4*)&sXt[k * XT_PITCH + ty * 4];
            float4 a1 = *(float4*)&sXt[k * XT_PITCH + 32 + ty * 4];
            float4 b0 = *(float4*)&sP[k * 128 + tx * 4];
            float4 b1 = *(float4*)&sP[k * 128 + 64 + tx * 4];
            mma8x8(acc2, a0, a1, b0, b1);
        }
    }

    #pragma unroll
    for (int i = 0; i < 8; i++) {
        const int c = (i >> 2) * 32 + ty * 4 + (i & 3);
        #pragma unroll
        for (int jh = 0; jh < 2; jh++) {
            const int m = m0 + jh * 64 + tx * 4;
            float2 p0 = unpack2(acc2[i][jh * 2 + 0]);
            float2 p1 = unpack2(acc2[i][jh * 2 + 1]);
            float4 v; v.x = p0.x; v.y = p0.y; v.z = p1.x; v.w = p1.y;
            *(float4*)&Ob[(size_t)c * LL + m] = v;
        }
    }
}
#define AV_SMEM_BYTES ((64 * XT_PITCH + 64 * 128) * 4)

// ---------------------------------------------------------------------------
extern "C" void kernel_launch(void* const* d_in, const int* in_sizes, int n_in,
                              void* d_out, int out_size)
{
    const float* x   = (const float*)d_in[0];
    const float* kw  = (const float*)d_in[1];
    const float* kb  = (const float*)d_in[2];
    const float* qw  = (const float*)d_in[3];
    const float* qb  = (const float*)d_in[4];
    const float* pw  = (const float*)d_in[5];
    const float* pb  = (const float*)d_in[6];
    const float* c1w = (const float*)d_in[7];
    const float* c1b = (const float*)d_in[8];
    const float* c2w = (const float*)d_in[9];
    const float* c2b = (const float*)d_in[10];
    float* out = (float*)d_out;

    float *gK, *gQ, *gS, *gAO, *gY, *gT;
    cudaGetSymbolAddress((void**)&gK,  g_K);
    cudaGetSymbolAddress((void**)&gQ,  g_Q);
    cudaGetSymbolAddress((void**)&gS,  g_S);
    cudaGetSymbolAddress((void**)&gAO, g_AO);
    cudaGetSymbolAddress((void**)&gY,  g_Y);
    cudaGetSymbolAddress((void**)&gT,  g_T);

    static bool attr_done = false;
    if (!attr_done) {
        cudaFuncSetAttribute(scores_kernel,
                             cudaFuncAttributeMaxDynamicSharedMemorySize,
                             SCORES_SMEM_BYTES);
        cudaFuncSetAttribute(av_kernel,
                             cudaFuncAttributeMaxDynamicSharedMemorySize,
                             AV_SMEM_BYTES);
        attr_done = true;
    }

    dim3 cgrid(LL / 128, CC / 128, BB);   // (16,8,2)
    dim3 cblk(256);

    // K and Q projections
    conv1x1_kernel<false, 0><<<cgrid, cblk>>>(kw, kb, x, gK, nullptr, nullptr);
    conv1x1_kernel<false, 0><<<cgrid, cblk>>>(qw, qb, x, gQ, nullptr, nullptr);

    // scores (scaled) -> softmax -> attention-weighted values
    scores_kernel<<<dim3(LL / 128, LL / 128, NBH), 256, SCORES_SMEM_BYTES>>>(gK, gQ, gS);
    softmax_kernel<<<(unsigned)SROWS, 256>>>(gS);
    av_kernel<<<dim3(LL / 128, NBH), 128, AV_SMEM_BYTES>>>(x, gS, gAO);

    // y = pconv(attn_out) + x
    conv1x1_kernel<false, 1><<<cgrid, cblk>>>(pw, pb, gAO, gY, x, nullptr);
    // t = relu(c1(y))
    conv1x1_kernel<true, 0><<<cgrid, cblk>>>(c1w, c1b, gY, gT, nullptr, nullptr);
    // out = c2(t) + y + x
    conv1x1_kernel<false, 2><<<cgrid, cblk>>>(c2w, c2b, gT, out, gY, x);
}

// round 6
// speedup vs baseline: 2.5773x; 1.2447x over previous
#include <cuda_runtime.h>
#include <cuda_bf16.h>
#include <cstdint>

// Problem constants
#define BB 2
#define CC 1024
#define LL 2048
#define HH 16
#define HD 64
#define BCL (BB*CC*LL)               // 4,194,304 floats
#define NBH (BB*HH)                  // 32
#define SROWS ((size_t)NBH * LL)     // 65536
#define SELEMS (SROWS * LL)          // 134,217,728 floats (512 MB)

// Scratch (device globals — runtime allocation is forbidden)
__device__ float g_K [BCL];
__device__ float g_Q [BCL];
__device__ float g_S [SELEMS];
__device__ float g_AO[BCL];
__device__ float g_Y [BCL];
__device__ float g_T [BCL];

// ---------------------------------------------------------------------------
// helpers
// ---------------------------------------------------------------------------
__device__ __forceinline__ uint32_t smem_u32(const void* p) {
    uint32_t a;
    asm("{ .reg .u64 t; cvta.to.shared.u64 t, %1; cvt.u32.u64 %0, t; }"
        : "=r"(a) : "l"(p));
    return a;
}
// bf16 split helpers
__device__ __forceinline__ uint32_t bf2_hi(float a, float b) {
    __nv_bfloat162 t = __floats2bfloat162_rn(a, b);
    return *reinterpret_cast<uint32_t*>(&t);
}
__device__ __forceinline__ float bf_res(float v) {   // v - bf16(v)
    __nv_bfloat16 h = __float2bfloat16(v);
    return v - __bfloat162float(h);
}

__device__ __forceinline__ void ldsm_x4(uint32_t r[4], uint32_t addr) {
    asm volatile("ldmatrix.sync.aligned.m8n8.x4.shared.b16 {%0,%1,%2,%3}, [%4];"
                 : "=r"(r[0]), "=r"(r[1]), "=r"(r[2]), "=r"(r[3]) : "r"(addr));
}
__device__ __forceinline__ void ldsm_x4_t(uint32_t r[4], uint32_t addr) {
    asm volatile("ldmatrix.sync.aligned.m8n8.x4.trans.shared.b16 {%0,%1,%2,%3}, [%4];"
                 : "=r"(r[0]), "=r"(r[1]), "=r"(r[2]), "=r"(r[3]) : "r"(addr));
}
__device__ __forceinline__ void mma_bf16(float c[4], const uint32_t a[4],
                                         const uint32_t b[2]) {
    asm volatile("mma.sync.aligned.m16n8k16.row.col.f32.bf16.bf16.f32 "
                 "{%0,%1,%2,%3}, {%4,%5,%6,%7}, {%8,%9}, {%0,%1,%2,%3};"
                 : "+f"(c[0]), "+f"(c[1]), "+f"(c[2]), "+f"(c[3])
                 : "r"(a[0]), "r"(a[1]), "r"(a[2]), "r"(a[3]),
                   "r"(b[0]), "r"(b[1]));
}

// ---------------------------------------------------------------------------
// Tensor-core (HMMA) conv1x1:
// Out[b,o,l] = sum_c W[o,c]*X[b,c,l] + bias[o]  (+A1 +A2, relu opt)
// Block tile M=128 (o) x N=128 (l), K chunked by 64; 256 thr = 8 warps,
// warp tile 32x64. bf16 two-term split (3 MMAs per fragment pair), fp32 acc.
// A = W rows (row-major, plain ldmatrix); B = X rows [c][l] (ldmatrix.trans).
// ---------------------------------------------------------------------------
#define APITCH 72    // bf16 per A row (144 B)
#define BPITCH 136   // bf16 per B row (272 B)
#define SM_AHI 0
#define SM_ALO (128 * APITCH)
#define SM_BHI (2 * 128 * APITCH)
#define SM_BLO (2 * 128 * APITCH + 64 * BPITCH)
#define CONV_SMEM ((2 * 128 * APITCH + 2 * 64 * BPITCH) * 2)   // 71,680 B

template<bool RELU, int NADD>
__global__ __launch_bounds__(256)
void conv_mma_kernel(const float* __restrict__ W, const float* __restrict__ bias,
                     const float* __restrict__ X, float* __restrict__ Out,
                     const float* __restrict__ A1, const float* __restrict__ A2)
{
    extern __shared__ __align__(16) __nv_bfloat16 smem[];
    __nv_bfloat16* sAhi = smem + SM_AHI;
    __nv_bfloat16* sAlo = smem + SM_ALO;
    __nv_bfloat16* sBhi = smem + SM_BHI;
    __nv_bfloat16* sBlo = smem + SM_BLO;
    const uint32_t uAhi = smem_u32(sAhi);
    const uint32_t uAlo = smem_u32(sAlo);
    const uint32_t uBhi = smem_u32(sBhi);
    const uint32_t uBlo = smem_u32(sBlo);

    const int b  = blockIdx.z;
    const int o0 = blockIdx.y * 128;
    const int l0 = blockIdx.x * 128;
    const float* Xb = X + (size_t)b * CC * LL;
    float* Ob = Out + (size_t)b * CC * LL;

    const int tid  = threadIdx.x;
    const int wid  = tid >> 5;
    const int lane = tid & 31;
    const int wm   = wid & 3;          // 4 M-groups of 32
    const int wn   = wid >> 2;         // 2 N-groups of 64

    // loader indices
    const int ar  = tid >> 4;          // A: row group 0..15
    const int ac4 = (tid & 15) * 4;    // A: col base
    const int bc  = tid >> 5;          // B: row group 0..7
    const int bl4 = (tid & 31) * 4;    // B: col base

    // ldmatrix per-lane addresses (element offsets; bytes = *2)
    const int a_row = wm * 32 + (lane & 15);
    const int a_col = ((lane >> 4) & 1) * 8;
    const int b_row = (lane & 15);
    const int b_colb = wn * 64 + ((lane >> 4) & 1) * 8;

    float acc[2][8][4];
    #pragma unroll
    for (int mi = 0; mi < 2; mi++)
        #pragma unroll
        for (int ni = 0; ni < 8; ni++)
            #pragma unroll
            for (int q = 0; q < 4; q++) acc[mi][ni][q] = 0.0f;

    for (int ci = 0; ci < CC / 64; ci++) {
        const int c0 = ci * 64;
        if (ci) __syncthreads();

        // --- load A tile: W[o0..o0+128)[c0..c0+64) -> sAhi/sAlo [o][c] ---
        #pragma unroll
        for (int p = 0; p < 8; p++) {
            const int row = ar + p * 16;
            float4 v = *(const float4*)&W[(size_t)(o0 + row) * CC + c0 + ac4];
            uint2 hi = make_uint2(bf2_hi(v.x, v.y), bf2_hi(v.z, v.w));
            uint2 lo = make_uint2(bf2_hi(bf_res(v.x), bf_res(v.y)),
                                  bf2_hi(bf_res(v.z), bf_res(v.w)));
            *(uint2*)&sAhi[row * APITCH + ac4] = hi;
            *(uint2*)&sAlo[row * APITCH + ac4] = lo;
        }
        // --- load B tile: X[c0..c0+64)[l0..l0+128) -> sBhi/sBlo [c][l] ---
        #pragma unroll
        for (int p = 0; p < 8; p++) {
            const int row = bc + p * 8;
            float4 v = *(const float4*)&Xb[(size_t)(c0 + row) * LL + l0 + bl4];
            uint2 hi = make_uint2(bf2_hi(v.x, v.y), bf2_hi(v.z, v.w));
            uint2 lo = make_uint2(bf2_hi(bf_res(v.x), bf_res(v.y)),
                                  bf2_hi(bf_res(v.z), bf_res(v.w)));
            *(uint2*)&sBhi[row * BPITCH + bl4] = hi;
            *(uint2*)&sBlo[row * BPITCH + bl4] = lo;
        }
        __syncthreads();

        #pragma unroll
        for (int ks = 0; ks < 4; ks++) {
            const int kb = ks * 16;
            uint32_t ahi[2][4], alo[2][4], bhi[8][2], blo[8][2];

            #pragma unroll
            for (int mi = 0; mi < 2; mi++) {
                const uint32_t off =
                    (uint32_t)((a_row + mi * 16) * APITCH + kb + a_col) * 2;
                ldsm_x4(ahi[mi], uAhi + off);
                ldsm_x4(alo[mi], uAlo + off);
            }
            #pragma unroll
            for (int nq = 0; nq < 4; nq++) {
                const uint32_t off =
                    (uint32_t)((kb + b_row) * BPITCH + b_colb + nq * 16) * 2;
                uint32_t th[4], tl[4];
                ldsm_x4_t(th, uBhi + off);
                ldsm_x4_t(tl, uBlo + off);
                bhi[nq * 2 + 0][0] = th[0]; bhi[nq * 2 + 0][1] = th[1];
                bhi[nq * 2 + 1][0] = th[2]; bhi[nq * 2 + 1][1] = th[3];
                blo[nq * 2 + 0][0] = tl[0]; blo[nq * 2 + 0][1] = tl[1];
                blo[nq * 2 + 1][0] = tl[2]; blo[nq * 2 + 1][1] = tl[3];
            }

            #pragma unroll
            for (int mi = 0; mi < 2; mi++)
                #pragma unroll
                for (int ni = 0; ni < 8; ni++) {
                    mma_bf16(acc[mi][ni], ahi[mi], bhi[ni]);
                    mma_bf16(acc[mi][ni], ahi[mi], blo[ni]);
                    mma_bf16(acc[mi][ni], alo[mi], bhi[ni]);
                }
        }
    }

    // --- epilogue: fragment c mapping: rows r,r+8 (r=lane>>2), cols 2g,2g+1 ---
    const int r = lane >> 2;
    const int g = lane & 3;
    const size_t boff = (size_t)b * CC * LL;

    #pragma unroll
    for (int mi = 0; mi < 2; mi++) {
        const int o1 = o0 + wm * 32 + mi * 16 + r;
        const int o2 = o1 + 8;
        const float bv1 = __ldg(&bias[o1]);
        const float bv2 = __ldg(&bias[o2]);
        #pragma unroll
        for (int ni = 0; ni < 8; ni++) {
            const int l = l0 + wn * 64 + ni * 8 + g * 2;
            float2 v01 = make_float2(acc[mi][ni][0] + bv1, acc[mi][ni][1] + bv1);
            float2 v23 = make_float2(acc[mi][ni][2] + bv2, acc[mi][ni][3] + bv2);
            if (RELU) {
                v01.x = fmaxf(v01.x, 0.f); v01.y = fmaxf(v01.y, 0.f);
                v23.x = fmaxf(v23.x, 0.f); v23.y = fmaxf(v23.y, 0.f);
            }
            const size_t i1 = (size_t)o1 * LL + l;
            const size_t i2 = (size_t)o2 * LL + l;
            if (NADD >= 1) {
                float2 a1v = *(const float2*)&A1[boff + i1];
                float2 a2v = *(const float2*)&A1[boff + i2];
                v01.x += a1v.x; v01.y += a1v.y;
                v23.x += a2v.x; v23.y += a2v.y;
            }
            if (NADD >= 2) {
                float2 a1v = *(const float2*)&A2[boff + i1];
                float2 a2v = *(const float2*)&A2[boff + i2];
                v01.x += a1v.x; v01.y += a1v.y;
                v23.x += a2v.x; v23.y += a2v.y;
            }
            *(float2*)&Ob[i1] = v01;
            *(float2*)&Ob[i2] = v23;
        }
    }
}

// ---------------------------------------------------------------------------
// Packed f32x2 helpers (Blackwell FFMA2) — attention path unchanged
// ---------------------------------------------------------------------------
typedef unsigned long long u64;

__device__ __forceinline__ u64 pack2(float x, float y) {
    u64 r; asm("mov.b64 %0, {%1, %2};" : "=l"(r) : "f"(x), "f"(y)); return r;
}
__device__ __forceinline__ float2 unpack2(u64 v) {
    float2 r; asm("mov.b64 {%0, %1}, %2;" : "=f"(r.x), "=f"(r.y) : "l"(v)); return r;
}
__device__ __forceinline__ void ffma2(u64& d, u64 a, u64 b) {
    asm("fma.rn.f32x2 %0, %1, %2, %0;" : "+l"(d) : "l"(a), "l"(b));
}
__device__ __forceinline__ void mma8x8(u64 acc2[8][4],
                                       float4 a0, float4 a1,
                                       float4 b0, float4 b1)
{
    u64 bp[4];
    bp[0] = pack2(b0.x, b0.y); bp[1] = pack2(b0.z, b0.w);
    bp[2] = pack2(b1.x, b1.y); bp[3] = pack2(b1.z, b1.w);
    float aa[8] = {a0.x, a0.y, a0.z, a0.w, a1.x, a1.y, a1.z, a1.w};
    #pragma unroll
    for (int i = 0; i < 8; i++) {
        u64 ad = pack2(aa[i], aa[i]);
        #pragma unroll
        for (int jp = 0; jp < 4; jp++)
            ffma2(acc2[i][jp], ad, bp[jp]);
    }
}

// ---------------------------------------------------------------------------
// scores: S[bh,l,m] = (1/1024) * sum_{c<64} K[bh,c,l] * Q[bh,c,m]
// ---------------------------------------------------------------------------
__global__ __launch_bounds__(256)
void scores_kernel(const float* __restrict__ K, const float* __restrict__ Q,
                   float* __restrict__ S)
{
    extern __shared__ float sm[];
    float* sK = sm;               // [64][128]  [c][l]
    float* sQ = sm + 64 * 128;    // [64][128]  [c][m]

    const int bh = blockIdx.z;
    const int b = bh >> 4, h = bh & 15;
    const int l0 = blockIdx.y * 128;
    const int m0 = blockIdx.x * 128;

    const size_t hoff = (size_t)b * CC * LL + (size_t)h * HD * LL;
    const float* Kb = K + hoff;
    const float* Qb = Q + hoff;
    float* Sb = S + (size_t)bh * LL * LL;

    const int tid = threadIdx.x;
    const int tx = tid & 15, ty = tid >> 4;
    const int lr  = tid >> 5;
    const int lc4 = (tid & 31) * 4;

    #pragma unroll
    for (int p = 0; p < 8; p++) {
        const int c = lr + p * 8;
        *(float4*)&sK[c * 128 + lc4] = *(const float4*)&Kb[(size_t)c * LL + l0 + lc4];
        *(float4*)&sQ[c * 128 + lc4] = *(const float4*)&Qb[(size_t)c * LL + m0 + lc4];
    }
    __syncthreads();

    u64 acc2[8][4];
    #pragma unroll
    for (int i = 0; i < 8; i++)
        #pragma unroll
        for (int j = 0; j < 4; j++) acc2[i][j] = 0ull;

    #pragma unroll 4
    for (int k = 0; k < 64; k++) {
        float4 a0 = *(float4*)&sK[k * 128 + ty * 4];
        float4 a1 = *(float4*)&sK[k * 128 + 64 + ty * 4];
        float4 b0 = *(float4*)&sQ[k * 128 + tx * 4];
        float4 b1 = *(float4*)&sQ[k * 128 + 64 + tx * 4];
        mma8x8(acc2, a0, a1, b0, b1);
    }

    const float scale = 1.0f / 1024.0f;
    #pragma unroll
    for (int i = 0; i < 8; i++) {
        const int l = l0 + (i >> 2) * 64 + ty * 4 + (i & 3);
        #pragma unroll
        for (int jh = 0; jh < 2; jh++) {
            const int m = m0 + jh * 64 + tx * 4;
            float2 p0 = unpack2(acc2[i][jh * 2 + 0]);
            float2 p1 = unpack2(acc2[i][jh * 2 + 1]);
            float4 v;
            v.x = p0.x * scale; v.y = p0.y * scale;
            v.z = p1.x * scale; v.w = p1.y * scale;
            *(float4*)&Sb[(size_t)l * LL + m] = v;
        }
    }
}
#define SCORES_SMEM_BYTES (2 * 64 * 128 * 4)

// ---------------------------------------------------------------------------
// softmax over last axis (2048), one block (256 thr) per row, in place
// ---------------------------------------------------------------------------
__device__ __forceinline__ float warp_rmax(float v) {
    #pragma unroll
    for (int o = 16; o > 0; o >>= 1) v = fmaxf(v, __shfl_xor_sync(0xffffffffu, v, o));
    return v;
}
__device__ __forceinline__ float warp_rsum(float v) {
    #pragma unroll
    for (int o = 16; o > 0; o >>= 1) v += __shfl_xor_sync(0xffffffffu, v, o);
    return v;
}

__global__ __launch_bounds__(256)
void softmax_kernel(float* __restrict__ S)
{
    const size_t row = blockIdx.x;
    float* p = S + row * LL;
    const int tid = threadIdx.x;
    const int lane = tid & 31, wid = tid >> 5;

    float4 v0 = reinterpret_cast<float4*>(p)[tid];
    float4 v1 = reinterpret_cast<float4*>(p)[tid + 256];

    float m = fmaxf(fmaxf(fmaxf(v0.x, v0.y), fmaxf(v0.z, v0.w)),
                    fmaxf(fmaxf(v1.x, v1.y), fmaxf(v1.z, v1.w)));

    __shared__ float sred[8];
    __shared__ float sbroad;

    m = warp_rmax(m);
    if (lane == 0) sred[wid] = m;
    __syncthreads();
    if (tid == 0) {
        float t = sred[0];
        #pragma unroll
        for (int i = 1; i < 8; i++) t = fmaxf(t, sred[i]);
        sbroad = t;
    }
    __syncthreads();
    const float mx = sbroad;
    __syncthreads();

    v0.x = __expf(v0.x - mx); v0.y = __expf(v0.y - mx);
    v0.z = __expf(v0.z - mx); v0.w = __expf(v0.w - mx);
    v1.x = __expf(v1.x - mx); v1.y = __expf(v1.y - mx);
    v1.z = __expf(v1.z - mx); v1.w = __expf(v1.w - mx);

    float s = (v0.x + v0.y + v0.z + v0.w) + (v1.x + v1.y + v1.z + v1.w);
    s = warp_rsum(s);
    if (lane == 0) sred[wid] = s;
    __syncthreads();
    if (tid == 0) {
        float t = 0.0f;
        #pragma unroll
        for (int i = 0; i < 8; i++) t += sred[i];
        sbroad = t;
    }
    __syncthreads();
    const float inv = 1.0f / sbroad;

    v0.x *= inv; v0.y *= inv; v0.z *= inv; v0.w *= inv;
    v1.x *= inv; v1.y *= inv; v1.z *= inv; v1.w *= inv;
    reinterpret_cast<float4*>(p)[tid]       = v0;
    reinterpret_cast<float4*>(p)[tid + 256] = v1;
}

// ---------------------------------------------------------------------------
// AV: O[bh,c,m] = sum_l X[bh,c,l] * A[bh,l,m]
// ---------------------------------------------------------------------------
#define XT_PITCH 68

__global__ __launch_bounds__(128)
void av_kernel(const float* __restrict__ X, const float* __restrict__ A,
               float* __restrict__ O)
{
    extern __shared__ float sm[];
    float* sXt = sm;                    // [64 l][68]
    float* sP  = sm + 64 * XT_PITCH;    // [64 l][128 m]

    const int bh = blockIdx.y;
    const int b = bh >> 4, h = bh & 15;
    const int m0 = blockIdx.x * 128;

    const size_t hoff = (size_t)b * CC * LL + (size_t)h * HD * LL;
    const float* Xb = X + hoff;
    const float* Ab = A + (size_t)bh * LL * LL;
    float* Ob = O + hoff;

    const int tid = threadIdx.x;
    const int tx = tid & 15, ty = tid >> 4;
    const int xc = tid & 63;
    const int xg = tid >> 6;
    const int pr = tid >> 5;
    const int pc4 = (tid & 31) * 4;

    u64 acc2[8][4];
    #pragma unroll
    for (int i = 0; i < 8; i++)
        #pragma unroll
        for (int j = 0; j < 4; j++) acc2[i][j] = 0ull;

    for (int l0 = 0; l0 < LL; l0 += 64) {
        __syncthreads();
        #pragma unroll
        for (int p = 0; p < 8; p++) {
            const int l4 = (xg + p * 2) * 4;
            float4 v = *(const float4*)&Xb[(size_t)xc * LL + l0 + l4];
            sXt[(l4 + 0) * XT_PITCH + xc] = v.x;
            sXt[(l4 + 1) * XT_PITCH + xc] = v.y;
            sXt[(l4 + 2) * XT_PITCH + xc] = v.z;
            sXt[(l4 + 3) * XT_PITCH + xc] = v.w;
        }
        #pragma unroll
        for (int p = 0; p < 16; p++) {
            const int r = pr + p * 4;
            *(float4*)&sP[r * 128 + pc4] =
                *(const float4*)&Ab[(size_t)(l0 + r) * LL + m0 + pc4];
        }
        __syncthreads();

        #pragma unroll 4
        for (int k = 0; k < 64; k++) {
            float4 a0 = *(float4*)&sXt[k * XT_PITCH + ty * 4];
            float4 a1 = *(float4*)&sXt[k * XT_PITCH + 32 + ty * 4];
            float4 b0 = *(float4*)&sP[k * 128 + tx * 4];
            float4 b1 = *(float4*)&sP[k * 128 + 64 + tx * 4];
            mma8x8(acc2, a0, a1, b0, b1);
        }
    }

    #pragma unroll
    for (int i = 0; i < 8; i++) {
        const int c = (i >> 2) * 32 + ty * 4 + (i & 3);
        #pragma unroll
        for (int jh = 0; jh < 2; jh++) {
            const int m = m0 + jh * 64 + tx * 4;
            float2 p0 = unpack2(acc2[i][jh * 2 + 0]);
            float2 p1 = unpack2(acc2[i][jh * 2 + 1]);
            float4 v; v.x = p0.x; v.y = p0.y; v.z = p1.x; v.w = p1.y;
            *(float4*)&Ob[(size_t)c * LL + m] = v;
        }
    }
}
#define AV_SMEM_BYTES ((64 * XT_PITCH + 64 * 128) * 4)

// ---------------------------------------------------------------------------
extern "C" void kernel_launch(void* const* d_in, const int* in_sizes, int n_in,
                              void* d_out, int out_size)
{
    const float* x   = (const float*)d_in[0];
    const float* kw  = (const float*)d_in[1];
    const float* kb  = (const float*)d_in[2];
    const float* qw  = (const float*)d_in[3];
    const float* qb  = (const float*)d_in[4];
    const float* pw  = (const float*)d_in[5];
    const float* pb  = (const float*)d_in[6];
    const float* c1w = (const float*)d_in[7];
    const float* c1b = (const float*)d_in[8];
    const float* c2w = (const float*)d_in[9];
    const float* c2b = (const float*)d_in[10];
    float* out = (float*)d_out;

    float *gK, *gQ, *gS, *gAO, *gY, *gT;
    cudaGetSymbolAddress((void**)&gK,  g_K);
    cudaGetSymbolAddress((void**)&gQ,  g_Q);
    cudaGetSymbolAddress((void**)&gS,  g_S);
    cudaGetSymbolAddress((void**)&gAO, g_AO);
    cudaGetSymbolAddress((void**)&gY,  g_Y);
    cudaGetSymbolAddress((void**)&gT,  g_T);

    static bool attr_done = false;
    if (!attr_done) {
        cudaFuncSetAttribute(scores_kernel,
                             cudaFuncAttributeMaxDynamicSharedMemorySize, SCORES_SMEM_BYTES);
        cudaFuncSetAttribute(av_kernel,
                             cudaFuncAttributeMaxDynamicSharedMemorySize, AV_SMEM_BYTES);
        cudaFuncSetAttribute(conv_mma_kernel<false, 0>,
                             cudaFuncAttributeMaxDynamicSharedMemorySize, CONV_SMEM);
        cudaFuncSetAttribute(conv_mma_kernel<false, 1>,
                             cudaFuncAttributeMaxDynamicSharedMemorySize, CONV_SMEM);
        cudaFuncSetAttribute(conv_mma_kernel<false, 2>,
                             cudaFuncAttributeMaxDynamicSharedMemorySize, CONV_SMEM);
        cudaFuncSetAttribute(conv_mma_kernel<true, 0>,
                             cudaFuncAttributeMaxDynamicSharedMemorySize, CONV_SMEM);
        attr_done = true;
    }

    dim3 cgrid(LL / 128, CC / 128, BB);   // (16,8,2)

    // K and Q projections (HMMA, bf16 split)
    conv_mma_kernel<false, 0><<<cgrid, 256, CONV_SMEM>>>(kw, kb, x, gK, nullptr, nullptr);
    conv_mma_kernel<false, 0><<<cgrid, 256, CONV_SMEM>>>(qw, qb, x, gQ, nullptr, nullptr);

    // scores (scaled) -> softmax -> attention-weighted values (FFMA2 path)
    scores_kernel<<<dim3(LL / 128, LL / 128, NBH), 256, SCORES_SMEM_BYTES>>>(gK, gQ, gS);
    softmax_kernel<<<(unsigned)SROWS, 256>>>(gS);
    av_kernel<<<dim3(LL / 128, NBH), 128, AV_SMEM_BYTES>>>(x, gS, gAO);

    // y = pconv(attn_out) + x
    conv_mma_kernel<false, 1><<<cgrid, 256, CONV_SMEM>>>(pw, pb, gAO, gY, x, nullptr);
    // t = relu(c1(y))
    conv_mma_kernel<true, 0><<<cgrid, 256, CONV_SMEM>>>(c1w, c1b, gY, gT, nullptr, nullptr);
    // out = c2(t) + y + x
    conv_mma_kernel<false, 2><<<cgrid, 256, CONV_SMEM>>>(c2w, c2b, gT, out, gY, x);
}

// round 7
// speedup vs baseline: 3.3362x; 1.2944x over previous
#include <cuda_runtime.h>
#include <cuda_bf16.h>
#include <cstdint>

// Problem constants
#define BB 2
#define CC 1024
#define LL 2048
#define HH 16
#define HD 64
#define BCL (BB*CC*LL)               // 4,194,304 floats
#define NBH (BB*HH)                  // 32
#define SROWS ((size_t)NBH * LL)     // 65536
#define SELEMS (SROWS * LL)          // 134,217,728 floats (512 MB)

// Scratch (device globals — runtime allocation is forbidden)
__device__ float g_K [BCL];
__device__ float g_Q [BCL];
__device__ float g_S [SELEMS];
__device__ float g_AO[BCL];
__device__ float g_Y [BCL];
__device__ float g_T [BCL];

// ---------------------------------------------------------------------------
// helpers
// ---------------------------------------------------------------------------
__device__ __forceinline__ uint32_t smem_u32(const void* p) {
    uint32_t a;
    asm("{ .reg .u64 t; cvta.to.shared.u64 t, %1; cvt.u32.u64 %0, t; }"
        : "=r"(a) : "l"(p));
    return a;
}
__device__ __forceinline__ uint32_t bf2_hi(float a, float b) {
    __nv_bfloat162 t = __floats2bfloat162_rn(a, b);
    return *reinterpret_cast<uint32_t*>(&t);
}
__device__ __forceinline__ float bf_res(float v) {   // v - bf16(v)
    __nv_bfloat16 h = __float2bfloat16(v);
    return v - __bfloat162float(h);
}

__device__ __forceinline__ void ldsm_x4(uint32_t r[4], uint32_t addr) {
    asm volatile("ldmatrix.sync.aligned.m8n8.x4.shared.b16 {%0,%1,%2,%3}, [%4];"
                 : "=r"(r[0]), "=r"(r[1]), "=r"(r[2]), "=r"(r[3]) : "r"(addr));
}
__device__ __forceinline__ void ldsm_x4_t(uint32_t r[4], uint32_t addr) {
    asm volatile("ldmatrix.sync.aligned.m8n8.x4.trans.shared.b16 {%0,%1,%2,%3}, [%4];"
                 : "=r"(r[0]), "=r"(r[1]), "=r"(r[2]), "=r"(r[3]) : "r"(addr));
}
__device__ __forceinline__ void mma_bf16(float c[4], const uint32_t a[4],
                                         const uint32_t b[2]) {
    asm volatile("mma.sync.aligned.m16n8k16.row.col.f32.bf16.bf16.f32 "
                 "{%0,%1,%2,%3}, {%4,%5,%6,%7}, {%8,%9}, {%0,%1,%2,%3};"
                 : "+f"(c[0]), "+f"(c[1]), "+f"(c[2]), "+f"(c[3])
                 : "r"(a[0]), "r"(a[1]), "r"(a[2]), "r"(a[3]),
                   "r"(b[0]), "r"(b[1]));
}

// ---------------------------------------------------------------------------
// Tensor-core (HMMA) conv1x1 — unchanged from R5 (verified)
// ---------------------------------------------------------------------------
#define APITCH 72    // bf16 per A row (144 B)
#define BPITCH 136   // bf16 per B row (272 B)
#define SM_AHI 0
#define SM_ALO (128 * APITCH)
#define SM_BHI (2 * 128 * APITCH)
#define SM_BLO (2 * 128 * APITCH + 64 * BPITCH)
#define CONV_SMEM ((2 * 128 * APITCH + 2 * 64 * BPITCH) * 2)   // 71,680 B

template<bool RELU, int NADD>
__global__ __launch_bounds__(256)
void conv_mma_kernel(const float* __restrict__ W, const float* __restrict__ bias,
                     const float* __restrict__ X, float* __restrict__ Out,
                     const float* __restrict__ A1, const float* __restrict__ A2)
{
    extern __shared__ __align__(16) __nv_bfloat16 smem[];
    __nv_bfloat16* sAhi = smem + SM_AHI;
    __nv_bfloat16* sAlo = smem + SM_ALO;
    __nv_bfloat16* sBhi = smem + SM_BHI;
    __nv_bfloat16* sBlo = smem + SM_BLO;
    const uint32_t uAhi = smem_u32(sAhi);
    const uint32_t uAlo = smem_u32(sAlo);
    const uint32_t uBhi = smem_u32(sBhi);
    const uint32_t uBlo = smem_u32(sBlo);

    const int b  = blockIdx.z;
    const int o0 = blockIdx.y * 128;
    const int l0 = blockIdx.x * 128;
    const float* Xb = X + (size_t)b * CC * LL;
    float* Ob = Out + (size_t)b * CC * LL;

    const int tid  = threadIdx.x;
    const int wid  = tid >> 5;
    const int lane = tid & 31;
    const int wm   = wid & 3;
    const int wn   = wid >> 2;

    const int ar  = tid >> 4;
    const int ac4 = (tid & 15) * 4;
    const int bc  = tid >> 5;
    const int bl4 = (tid & 31) * 4;

    const int a_row = wm * 32 + (lane & 15);
    const int a_col = ((lane >> 4) & 1) * 8;
    const int b_row = (lane & 15);
    const int b_colb = wn * 64 + ((lane >> 4) & 1) * 8;

    float acc[2][8][4];
    #pragma unroll
    for (int mi = 0; mi < 2; mi++)
        #pragma unroll
        for (int ni = 0; ni < 8; ni++)
            #pragma unroll
            for (int q = 0; q < 4; q++) acc[mi][ni][q] = 0.0f;

    for (int ci = 0; ci < CC / 64; ci++) {
        const int c0 = ci * 64;
        if (ci) __syncthreads();

        #pragma unroll
        for (int p = 0; p < 8; p++) {
            const int row = ar + p * 16;
            float4 v = *(const float4*)&W[(size_t)(o0 + row) * CC + c0 + ac4];
            uint2 hi = make_uint2(bf2_hi(v.x, v.y), bf2_hi(v.z, v.w));
            uint2 lo = make_uint2(bf2_hi(bf_res(v.x), bf_res(v.y)),
                                  bf2_hi(bf_res(v.z), bf_res(v.w)));
            *(uint2*)&sAhi[row * APITCH + ac4] = hi;
            *(uint2*)&sAlo[row * APITCH + ac4] = lo;
        }
        #pragma unroll
        for (int p = 0; p < 8; p++) {
            const int row = bc + p * 8;
            float4 v = *(const float4*)&Xb[(size_t)(c0 + row) * LL + l0 + bl4];
            uint2 hi = make_uint2(bf2_hi(v.x, v.y), bf2_hi(v.z, v.w));
            uint2 lo = make_uint2(bf2_hi(bf_res(v.x), bf_res(v.y)),
                                  bf2_hi(bf_res(v.z), bf_res(v.w)));
            *(uint2*)&sBhi[row * BPITCH + bl4] = hi;
            *(uint2*)&sBlo[row * BPITCH + bl4] = lo;
        }
        __syncthreads();

        #pragma unroll
        for (int ks = 0; ks < 4; ks++) {
            const int kb = ks * 16;
            uint32_t ahi[2][4], alo[2][4], bhi[8][2], blo[8][2];

            #pragma unroll
            for (int mi = 0; mi < 2; mi++) {
                const uint32_t off =
                    (uint32_t)((a_row + mi * 16) * APITCH + kb + a_col) * 2;
                ldsm_x4(ahi[mi], uAhi + off);
                ldsm_x4(alo[mi], uAlo + off);
            }
            #pragma unroll
            for (int nq = 0; nq < 4; nq++) {
                const uint32_t off =
                    (uint32_t)((kb + b_row) * BPITCH + b_colb + nq * 16) * 2;
                uint32_t th[4], tl[4];
                ldsm_x4_t(th, uBhi + off);
                ldsm_x4_t(tl, uBlo + off);
                bhi[nq * 2 + 0][0] = th[0]; bhi[nq * 2 + 0][1] = th[1];
                bhi[nq * 2 + 1][0] = th[2]; bhi[nq * 2 + 1][1] = th[3];
                blo[nq * 2 + 0][0] = tl[0]; blo[nq * 2 + 0][1] = tl[1];
                blo[nq * 2 + 1][0] = tl[2]; blo[nq * 2 + 1][1] = tl[3];
            }

            #pragma unroll
            for (int mi = 0; mi < 2; mi++)
                #pragma unroll
                for (int ni = 0; ni < 8; ni++) {
                    mma_bf16(acc[mi][ni], ahi[mi], bhi[ni]);
                    mma_bf16(acc[mi][ni], ahi[mi], blo[ni]);
                    mma_bf16(acc[mi][ni], alo[mi], bhi[ni]);
                }
        }
    }

    const int r = lane >> 2;
    const int g = lane & 3;
    const size_t boff = (size_t)b * CC * LL;

    #pragma unroll
    for (int mi = 0; mi < 2; mi++) {
        const int o1 = o0 + wm * 32 + mi * 16 + r;
        const int o2 = o1 + 8;
        const float bv1 = __ldg(&bias[o1]);
        const float bv2 = __ldg(&bias[o2]);
        #pragma unroll
        for (int ni = 0; ni < 8; ni++) {
            const int l = l0 + wn * 64 + ni * 8 + g * 2;
            float2 v01 = make_float2(acc[mi][ni][0] + bv1, acc[mi][ni][1] + bv1);
            float2 v23 = make_float2(acc[mi][ni][2] + bv2, acc[mi][ni][3] + bv2);
            if (RELU) {
                v01.x = fmaxf(v01.x, 0.f); v01.y = fmaxf(v01.y, 0.f);
                v23.x = fmaxf(v23.x, 0.f); v23.y = fmaxf(v23.y, 0.f);
            }
            const size_t i1 = (size_t)o1 * LL + l;
            const size_t i2 = (size_t)o2 * LL + l;
            if (NADD >= 1) {
                float2 a1v = *(const float2*)&A1[boff + i1];
                float2 a2v = *(const float2*)&A1[boff + i2];
                v01.x += a1v.x; v01.y += a1v.y;
                v23.x += a2v.x; v23.y += a2v.y;
            }
            if (NADD >= 2) {
                float2 a1v = *(const float2*)&A2[boff + i1];
                float2 a2v = *(const float2*)&A2[boff + i2];
                v01.x += a1v.x; v01.y += a1v.y;
                v23.x += a2v.x; v23.y += a2v.y;
            }
            *(float2*)&Ob[i1] = v01;
            *(float2*)&Ob[i2] = v23;
        }
    }
}

// ---------------------------------------------------------------------------
// HMMA scores: S[bh,l,m] = (1/1024) * sum_{c<64} K[bh,c,l] * Q[bh,c,m]
// Block 128(l) x 128(m), 256 thr (8 warps, warp tile 32x64).
// A = K^T via ldmatrix.trans; B = Q via ldmatrix.trans. bf16 split, fp32 acc.
// ---------------------------------------------------------------------------
#define SPITCH 136
#define SC_KHI 0
#define SC_KLO (64 * SPITCH)
#define SC_QHI (2 * 64 * SPITCH)
#define SC_QLO (3 * 64 * SPITCH)
#define SCORES_SMEM (4 * 64 * SPITCH * 2)   // 69,632 B

__global__ __launch_bounds__(256)
void scores_mma_kernel(const float* __restrict__ K, const float* __restrict__ Q,
                       float* __restrict__ S)
{
    extern __shared__ __align__(16) __nv_bfloat16 smem[];
    __nv_bfloat16* sKhi = smem + SC_KHI;
    __nv_bfloat16* sKlo = smem + SC_KLO;
    __nv_bfloat16* sQhi = smem + SC_QHI;
    __nv_bfloat16* sQlo = smem + SC_QLO;
    const uint32_t uKhi = smem_u32(sKhi);
    const uint32_t uKlo = smem_u32(sKlo);
    const uint32_t uQhi = smem_u32(sQhi);
    const uint32_t uQlo = smem_u32(sQlo);

    const int bh = blockIdx.z;
    const int b = bh >> 4, h = bh & 15;
    const int l0 = blockIdx.y * 128;
    const int m0 = blockIdx.x * 128;

    const size_t hoff = (size_t)b * CC * LL + (size_t)h * HD * LL;
    const float* Kb = K + hoff;
    const float* Qb = Q + hoff;
    float* Sb = S + (size_t)bh * LL * LL;

    const int tid  = threadIdx.x;
    const int wid  = tid >> 5;
    const int lane = tid & 31;
    const int wm   = wid & 3;           // l group of 32
    const int wn   = wid >> 2;          // m group of 64

    // loaders: 64 rows x 128 cols each, 256 threads
    const int lr  = tid >> 5;           // row base 0..7
    const int lc4 = (tid & 31) * 4;

    #pragma unroll
    for (int p = 0; p < 8; p++) {
        const int row = lr + p * 8;     // c index
        float4 vk = *(const float4*)&Kb[(size_t)row * LL + l0 + lc4];
        float4 vq = *(const float4*)&Qb[(size_t)row * LL + m0 + lc4];
        *(uint2*)&sKhi[row * SPITCH + lc4] =
            make_uint2(bf2_hi(vk.x, vk.y), bf2_hi(vk.z, vk.w));
        *(uint2*)&sKlo[row * SPITCH + lc4] =
            make_uint2(bf2_hi(bf_res(vk.x), bf_res(vk.y)),
                       bf2_hi(bf_res(vk.z), bf_res(vk.w)));
        *(uint2*)&sQhi[row * SPITCH + lc4] =
            make_uint2(bf2_hi(vq.x, vq.y), bf2_hi(vq.z, vq.w));
        *(uint2*)&sQlo[row * SPITCH + lc4] =
            make_uint2(bf2_hi(bf_res(vq.x), bf_res(vq.y)),
                       bf2_hi(bf_res(vq.z), bf_res(vq.w)));
    }
    __syncthreads();

    // A (K^T) trans-ldmatrix lane addressing: mat order -> a0..a3
    const int a_krow = (lane & 7) + ((lane >> 4) & 1) * 8;
    const int a_mcol = wm * 32 + ((lane >> 3) & 1) * 8;
    // B (Q) trans lane addressing (conv-verified pattern)
    const int b_krow = (lane & 15);
    const int b_mcol = wn * 64 + ((lane >> 4) & 1) * 8;

    float acc[2][8][4];
    #pragma unroll
    for (int mi = 0; mi < 2; mi++)
        #pragma unroll
        for (int ni = 0; ni < 8; ni++)
            #pragma unroll
            for (int q = 0; q < 4; q++) acc[mi][ni][q] = 0.0f;

    #pragma unroll
    for (int ks = 0; ks < 4; ks++) {
        const int kb = ks * 16;
        uint32_t ahi[2][4], alo[2][4], bhi[8][2], blo[8][2];

        #pragma unroll
        for (int mi = 0; mi < 2; mi++) {
            const uint32_t off =
                (uint32_t)((kb + a_krow) * SPITCH + a_mcol + mi * 16) * 2;
            ldsm_x4_t(ahi[mi], uKhi + off);
            ldsm_x4_t(alo[mi], uKlo + off);
        }
        #pragma unroll
        for (int nq = 0; nq < 4; nq++) {
            const uint32_t off =
                (uint32_t)((kb + b_krow) * SPITCH + b_mcol + nq * 16) * 2;
            uint32_t th[4], tl[4];
            ldsm_x4_t(th, uQhi + off);
            ldsm_x4_t(tl, uQlo + off);
            bhi[nq * 2 + 0][0] = th[0]; bhi[nq * 2 + 0][1] = th[1];
            bhi[nq * 2 + 1][0] = th[2]; bhi[nq * 2 + 1][1] = th[3];
            blo[nq * 2 + 0][0] = tl[0]; blo[nq * 2 + 0][1] = tl[1];
            blo[nq * 2 + 1][0] = tl[2]; blo[nq * 2 + 1][1] = tl[3];
        }

        #pragma unroll
        for (int mi = 0; mi < 2; mi++)
            #pragma unroll
            for (int ni = 0; ni < 8; ni++) {
                mma_bf16(acc[mi][ni], ahi[mi], bhi[ni]);
                mma_bf16(acc[mi][ni], ahi[mi], blo[ni]);
                mma_bf16(acc[mi][ni], alo[mi], bhi[ni]);
            }
    }

    const int r = lane >> 2;
    const int g = lane & 3;
    const float scale = 1.0f / 1024.0f;   // softmax(scores / (L/2))

    #pragma unroll
    for (int mi = 0; mi < 2; mi++) {
        const int l1 = l0 + wm * 32 + mi * 16 + r;
        const int l2 = l1 + 8;
        #pragma unroll
        for (int ni = 0; ni < 8; ni++) {
            const int m = m0 + wn * 64 + ni * 8 + g * 2;
            float2 v01 = make_float2(acc[mi][ni][0] * scale, acc[mi][ni][1] * scale);
            float2 v23 = make_float2(acc[mi][ni][2] * scale, acc[mi][ni][3] * scale);
            *(float2*)&Sb[(size_t)l1 * LL + m] = v01;
            *(float2*)&Sb[(size_t)l2 * LL + m] = v23;
        }
    }
}

// ---------------------------------------------------------------------------
// softmax over last axis (2048), one block (256 thr) per row, in place
// ---------------------------------------------------------------------------
__device__ __forceinline__ float warp_rmax(float v) {
    #pragma unroll
    for (int o = 16; o > 0; o >>= 1) v = fmaxf(v, __shfl_xor_sync(0xffffffffu, v, o));
    return v;
}
__device__ __forceinline__ float warp_rsum(float v) {
    #pragma unroll
    for (int o = 16; o > 0; o >>= 1) v += __shfl_xor_sync(0xffffffffu, v, o);
    return v;
}

__global__ __launch_bounds__(256)
void softmax_kernel(float* __restrict__ S)
{
    const size_t row = blockIdx.x;
    float* p = S + row * LL;
    const int tid = threadIdx.x;
    const int lane = tid & 31, wid = tid >> 5;

    float4 v0 = reinterpret_cast<float4*>(p)[tid];
    float4 v1 = reinterpret_cast<float4*>(p)[tid + 256];

    float m = fmaxf(fmaxf(fmaxf(v0.x, v0.y), fmaxf(v0.z, v0.w)),
                    fmaxf(fmaxf(v1.x, v1.y), fmaxf(v1.z, v1.w)));

    __shared__ float sred[8];
    __shared__ float sbroad;

    m = warp_rmax(m);
    if (lane == 0) sred[wid] = m;
    __syncthreads();
    if (tid == 0) {
        float t = sred[0];
        #pragma unroll
        for (int i = 1; i < 8; i++) t = fmaxf(t, sred[i]);
        sbroad = t;
    }
    __syncthreads();
    const float mx = sbroad;
    __syncthreads();

    v0.x = __expf(v0.x - mx); v0.y = __expf(v0.y - mx);
    v0.z = __expf(v0.z - mx); v0.w = __expf(v0.w - mx);
    v1.x = __expf(v1.x - mx); v1.y = __expf(v1.y - mx);
    v1.z = __expf(v1.z - mx); v1.w = __expf(v1.w - mx);

    float s = (v0.x + v0.y + v0.z + v0.w) + (v1.x + v1.y + v1.z + v1.w);
    s = warp_rsum(s);
    if (lane == 0) sred[wid] = s;
    __syncthreads();
    if (tid == 0) {
        float t = 0.0f;
        #pragma unroll
        for (int i = 0; i < 8; i++) t += sred[i];
        sbroad = t;
    }
    __syncthreads();
    const float inv = 1.0f / sbroad;

    v0.x *= inv; v0.y *= inv; v0.z *= inv; v0.w *= inv;
    v1.x *= inv; v1.y *= inv; v1.z *= inv; v1.w *= inv;
    reinterpret_cast<float4*>(p)[tid]       = v0;
    reinterpret_cast<float4*>(p)[tid + 256] = v1;
}

// ---------------------------------------------------------------------------
// HMMA AV: O[bh,c,m] = sum_l X[bh,c,l] * A[bh,l,m]
// Block 64(c) x 128(m), 256 thr (8 warps, warp tile 16x64). l chunks of 64.
// A = X rows (plain ldmatrix); B = P rows (trans). fp32 P split in-kernel.
// ---------------------------------------------------------------------------
#define XP 72
#define PP 136
#define AV_XHI 0
#define AV_XLO (64 * XP)
#define AV_PHI (2 * 64 * XP)
#define AV_PLO (2 * 64 * XP + 64 * PP)
#define AV_SMEM ((2 * 64 * XP + 2 * 64 * PP) * 2)   // 53,248 B

__global__ __launch_bounds__(256)
void av_mma_kernel(const float* __restrict__ X, const float* __restrict__ A,
                   float* __restrict__ O)
{
    extern __shared__ __align__(16) __nv_bfloat16 smem[];
    __nv_bfloat16* sXhi = smem + AV_XHI;
    __nv_bfloat16* sXlo = smem + AV_XLO;
    __nv_bfloat16* sPhi = smem + AV_PHI;
    __nv_bfloat16* sPlo = smem + AV_PLO;
    const uint32_t uXhi = smem_u32(sXhi);
    const uint32_t uXlo = smem_u32(sXlo);
    const uint32_t uPhi = smem_u32(sPhi);
    const uint32_t uPlo = smem_u32(sPlo);

    const int bh = blockIdx.y;
    const int b = bh >> 4, h = bh & 15;
    const int m0 = blockIdx.x * 128;

    const size_t hoff = (size_t)b * CC * LL + (size_t)h * HD * LL;
    const float* Xb = X + hoff;
    const float* Ab = A + (size_t)bh * LL * LL;
    float* Ob = O + hoff;

    const int tid  = threadIdx.x;
    const int wid  = tid >> 5;
    const int lane = tid & 31;
    const int wm   = wid & 3;          // c group of 16
    const int wn   = wid >> 2;         // m group of 64

    // X loader: 64 rows x 64 cols, 256 thr -> 1 float4 x 4 iters
    const int xr  = tid >> 4;          // 0..15
    const int xc4 = (tid & 15) * 4;
    // P loader: 64 rows x 128 cols, 256 thr -> 1 float4 x 8 iters
    const int pr  = tid >> 5;          // 0..7
    const int pc4 = (tid & 31) * 4;

    // A (X) plain-ldmatrix lane addressing
    const int a_row = wm * 16 + (lane & 15);
    const int a_col = ((lane >> 4) & 1) * 8;
    // B (P) trans lane addressing
    const int b_krow = (lane & 15);
    const int b_mcol = wn * 64 + ((lane >> 4) & 1) * 8;

    float acc[8][4];
    #pragma unroll
    for (int ni = 0; ni < 8; ni++)
        #pragma unroll
        for (int q = 0; q < 4; q++) acc[ni][q] = 0.0f;

    for (int l0 = 0; l0 < LL; l0 += 64) {
        if (l0) __syncthreads();

        #pragma unroll
        for (int p = 0; p < 4; p++) {
            const int row = xr + p * 16;      // c
            float4 v = *(const float4*)&Xb[(size_t)row * LL + l0 + xc4];
            *(uint2*)&sXhi[row * XP + xc4] =
                make_uint2(bf2_hi(v.x, v.y), bf2_hi(v.z, v.w));
            *(uint2*)&sXlo[row * XP + xc4] =
                make_uint2(bf2_hi(bf_res(v.x), bf_res(v.y)),
                           bf2_hi(bf_res(v.z), bf_res(v.w)));
        }
        #pragma unroll
        for (int p = 0; p < 8; p++) {
            const int row = pr + p * 8;       // l within chunk
            float4 v = *(const float4*)&Ab[(size_t)(l0 + row) * LL + m0 + pc4];
            *(uint2*)&sPhi[row * PP + pc4] =
                make_uint2(bf2_hi(v.x, v.y), bf2_hi(v.z, v.w));
            *(uint2*)&sPlo[row * PP + pc4] =
                make_uint2(bf2_hi(bf_res(v.x), bf_res(v.y)),
                           bf2_hi(bf_res(v.z), bf_res(v.w)));
        }
        __syncthreads();

        #pragma unroll
        for (int ks = 0; ks < 4; ks++) {
            const int kb = ks * 16;
            uint32_t ahi[4], alo[4], bhi[8][2], blo[8][2];

            {
                const uint32_t off = (uint32_t)(a_row * XP + kb + a_col) * 2;
                ldsm_x4(ahi, uXhi + off);
                ldsm_x4(alo, uXlo + off);
            }
            #pragma unroll
            for (int nq = 0; nq < 4; nq++) {
                const uint32_t off =
                    (uint32_t)((kb + b_krow) * PP + b_mcol + nq * 16) * 2;
                uint32_t th[4], tl[4];
                ldsm_x4_t(th, uPhi + off);
                ldsm_x4_t(tl, uPlo + off);
                bhi[nq * 2 + 0][0] = th[0]; bhi[nq * 2 + 0][1] = th[1];
                bhi[nq * 2 + 1][0] = th[2]; bhi[nq * 2 + 1][1] = th[3];
                blo[nq * 2 + 0][0] = tl[0]; blo[nq * 2 + 0][1] = tl[1];
                blo[nq * 2 + 1][0] = tl[2]; blo[nq * 2 + 1][1] = tl[3];
            }

            #pragma unroll
            for (int ni = 0; ni < 8; ni++) {
                mma_bf16(acc[ni], ahi, bhi[ni]);
                mma_bf16(acc[ni], ahi, blo[ni]);
                mma_bf16(acc[ni], alo, bhi[ni]);
            }
        }
    }

    const int r = lane >> 2;
    const int g = lane & 3;
    const int c1 = wm * 16 + r;
    const int c2 = c1 + 8;

    #pragma unroll
    for (int ni = 0; ni < 8; ni++) {
        const int m = m0 + wn * 64 + ni * 8 + g * 2;
        *(float2*)&Ob[(size_t)c1 * LL + m] = make_float2(acc[ni][0], acc[ni][1]);
        *(float2*)&Ob[(size_t)c2 * LL + m] = make_float2(acc[ni][2], acc[ni][3]);
    }
}

// ---------------------------------------------------------------------------
extern "C" void kernel_launch(void* const* d_in, const int* in_sizes, int n_in,
                              void* d_out, int out_size)
{
    const float* x   = (const float*)d_in[0];
    const float* kw  = (const float*)d_in[1];
    const float* kb  = (const float*)d_in[2];
    const float* qw  = (const float*)d_in[3];
    const float* qb  = (const float*)d_in[4];
    const float* pw  = (const float*)d_in[5];
    const float* pb  = (const float*)d_in[6];
    const float* c1w = (const float*)d_in[7];
    const float* c1b = (const float*)d_in[8];
    const float* c2w = (const float*)d_in[9];
    const float* c2b = (const float*)d_in[10];
    float* out = (float*)d_out;

    float *gK, *gQ, *gS, *gAO, *gY, *gT;
    cudaGetSymbolAddress((void**)&gK,  g_K);
    cudaGetSymbolAddress((void**)&gQ,  g_Q);
    cudaGetSymbolAddress((void**)&gS,  g_S);
    cudaGetSymbolAddress((void**)&gAO, g_AO);
    cudaGetSymbolAddress((void**)&gY,  g_Y);
    cudaGetSymbolAddress((void**)&gT,  g_T);

    static bool attr_done = false;
    if (!attr_done) {
        cudaFuncSetAttribute(scores_mma_kernel,
                             cudaFuncAttributeMaxDynamicSharedMemorySize, SCORES_SMEM);
        cudaFuncSetAttribute(av_mma_kernel,
                             cudaFuncAttributeMaxDynamicSharedMemorySize, AV_SMEM);
        cudaFuncSetAttribute(conv_mma_kernel<false, 0>,
                             cudaFuncAttributeMaxDynamicSharedMemorySize, CONV_SMEM);
        cudaFuncSetAttribute(conv_mma_kernel<false, 1>,
                             cudaFuncAttributeMaxDynamicSharedMemorySize, CONV_SMEM);
        cudaFuncSetAttribute(conv_mma_kernel<false, 2>,
                             cudaFuncAttributeMaxDynamicSharedMemorySize, CONV_SMEM);
        cudaFuncSetAttribute(conv_mma_kernel<true, 0>,
                             cudaFuncAttributeMaxDynamicSharedMemorySize, CONV_SMEM);
        attr_done = true;
    }

    dim3 cgrid(LL / 128, CC / 128, BB);   // (16,8,2)

    // K and Q projections (HMMA, bf16 split)
    conv_mma_kernel<false, 0><<<cgrid, 256, CONV_SMEM>>>(kw, kb, x, gK, nullptr, nullptr);
    conv_mma_kernel<false, 0><<<cgrid, 256, CONV_SMEM>>>(qw, qb, x, gQ, nullptr, nullptr);

    // scores (HMMA) -> softmax -> AV (HMMA)
    scores_mma_kernel<<<dim3(LL / 128, LL / 128, NBH), 256, SCORES_SMEM>>>(gK, gQ, gS);
    softmax_kernel<<<(unsigned)SROWS, 256>>>(gS);
    av_mma_kernel<<<dim3(LL / 128, NBH), 256, AV_SMEM>>>(x, gS, gAO);

    // y = pconv(attn_out) + x
    conv_mma_kernel<false, 1><<<cgrid, 256, CONV_SMEM>>>(pw, pb, gAO, gY, x, nullptr);
    // t = relu(c1(y))
    conv_mma_kernel<true, 0><<<cgrid, 256, CONV_SMEM>>>(c1w, c1b, gY, gT, nullptr, nullptr);
    // out = c2(t) + y + x
    conv_mma_kernel<false, 2><<<cgrid, 256, CONV_SMEM>>>(c2w, c2b, gT, out, gY, x);
}

// round 8
// speedup vs baseline: 3.8928x; 1.1668x over previous
#include <cuda_runtime.h>
#include <cuda_bf16.h>
#include <cstdint>

// Problem constants
#define BB 2
#define CC 1024
#define LL 2048
#define HH 16
#define HD 64
#define BCL (BB*CC*LL)               // 4,194,304 floats
#define NBH (BB*HH)                  // 32
#define SROWS ((size_t)NBH * LL)     // 65536
#define SELEMS (SROWS * LL)          // 134,217,728 elems (256 MB bf16)

// Scratch (device globals — runtime allocation is forbidden)
__device__ float         g_K [BCL];
__device__ float         g_Q [BCL];
__device__ __nv_bfloat16 g_S [SELEMS];
__device__ float         g_AO[BCL];
__device__ float         g_Y [BCL];
__device__ float         g_T [BCL];

// ---------------------------------------------------------------------------
// helpers
// ---------------------------------------------------------------------------
__device__ __forceinline__ uint32_t smem_u32(const void* p) {
    uint32_t a;
    asm("{ .reg .u64 t; cvta.to.shared.u64 t, %1; cvt.u32.u64 %0, t; }"
        : "=r"(a) : "l"(p));
    return a;
}
__device__ __forceinline__ uint32_t bf2_hi(float a, float b) {
    __nv_bfloat162 t = __floats2bfloat162_rn(a, b);
    return *reinterpret_cast<uint32_t*>(&t);
}
__device__ __forceinline__ float bf_res(float v) {   // v - bf16(v)
    __nv_bfloat16 h = __float2bfloat16(v);
    return v - __bfloat162float(h);
}

__device__ __forceinline__ void ldsm_x4(uint32_t r[4], uint32_t addr) {
    asm volatile("ldmatrix.sync.aligned.m8n8.x4.shared.b16 {%0,%1,%2,%3}, [%4];"
                 : "=r"(r[0]), "=r"(r[1]), "=r"(r[2]), "=r"(r[3]) : "r"(addr));
}
__device__ __forceinline__ void ldsm_x4_t(uint32_t r[4], uint32_t addr) {
    asm volatile("ldmatrix.sync.aligned.m8n8.x4.trans.shared.b16 {%0,%1,%2,%3}, [%4];"
                 : "=r"(r[0]), "=r"(r[1]), "=r"(r[2]), "=r"(r[3]) : "r"(addr));
}
__device__ __forceinline__ void mma_bf16(float c[4], const uint32_t a[4],
                                         const uint32_t b[2]) {
    asm volatile("mma.sync.aligned.m16n8k16.row.col.f32.bf16.bf16.f32 "
                 "{%0,%1,%2,%3}, {%4,%5,%6,%7}, {%8,%9}, {%0,%1,%2,%3};"
                 : "+f"(c[0]), "+f"(c[1]), "+f"(c[2]), "+f"(c[3])
                 : "r"(a[0]), "r"(a[1]), "r"(a[2]), "r"(a[3]),
                   "r"(b[0]), "r"(b[1]));
}

// ---------------------------------------------------------------------------
// Tensor-core (HMMA) conv1x1 — unchanged from R5/R6 (verified)
// ---------------------------------------------------------------------------
#define APITCH 72    // bf16 per A row (144 B)
#define BPITCH 136   // bf16 per B row (272 B)
#define SM_AHI 0
#define SM_ALO (128 * APITCH)
#define SM_BHI (2 * 128 * APITCH)
#define SM_BLO (2 * 128 * APITCH + 64 * BPITCH)
#define CONV_SMEM ((2 * 128 * APITCH + 2 * 64 * BPITCH) * 2)   // 71,680 B

template<bool RELU, int NADD>
__global__ __launch_bounds__(256)
void conv_mma_kernel(const float* __restrict__ W, const float* __restrict__ bias,
                     const float* __restrict__ X, float* __restrict__ Out,
                     const float* __restrict__ A1, const float* __restrict__ A2)
{
    extern __shared__ __align__(16) __nv_bfloat16 smem[];
    __nv_bfloat16* sAhi = smem + SM_AHI;
    __nv_bfloat16* sAlo = smem + SM_ALO;
    __nv_bfloat16* sBhi = smem + SM_BHI;
    __nv_bfloat16* sBlo = smem + SM_BLO;
    const uint32_t uAhi = smem_u32(sAhi);
    const uint32_t uAlo = smem_u32(sAlo);
    const uint32_t uBhi = smem_u32(sBhi);
    const uint32_t uBlo = smem_u32(sBlo);

    const int b  = blockIdx.z;
    const int o0 = blockIdx.y * 128;
    const int l0 = blockIdx.x * 128;
    const float* Xb = X + (size_t)b * CC * LL;
    float* Ob = Out + (size_t)b * CC * LL;

    const int tid  = threadIdx.x;
    const int wid  = tid >> 5;
    const int lane = tid & 31;
    const int wm   = wid & 3;
    const int wn   = wid >> 2;

    const int ar  = tid >> 4;
    const int ac4 = (tid & 15) * 4;
    const int bc  = tid >> 5;
    const int bl4 = (tid & 31) * 4;

    const int a_row = wm * 32 + (lane & 15);
    const int a_col = ((lane >> 4) & 1) * 8;
    const int b_row = (lane & 15);
    const int b_colb = wn * 64 + ((lane >> 4) & 1) * 8;

    float acc[2][8][4];
    #pragma unroll
    for (int mi = 0; mi < 2; mi++)
        #pragma unroll
        for (int ni = 0; ni < 8; ni++)
            #pragma unroll
            for (int q = 0; q < 4; q++) acc[mi][ni][q] = 0.0f;

    for (int ci = 0; ci < CC / 64; ci++) {
        const int c0 = ci * 64;
        if (ci) __syncthreads();

        #pragma unroll
        for (int p = 0; p < 8; p++) {
            const int row = ar + p * 16;
            float4 v = *(const float4*)&W[(size_t)(o0 + row) * CC + c0 + ac4];
            uint2 hi = make_uint2(bf2_hi(v.x, v.y), bf2_hi(v.z, v.w));
            uint2 lo = make_uint2(bf2_hi(bf_res(v.x), bf_res(v.y)),
                                  bf2_hi(bf_res(v.z), bf_res(v.w)));
            *(uint2*)&sAhi[row * APITCH + ac4] = hi;
            *(uint2*)&sAlo[row * APITCH + ac4] = lo;
        }
        #pragma unroll
        for (int p = 0; p < 8; p++) {
            const int row = bc + p * 8;
            float4 v = *(const float4*)&Xb[(size_t)(c0 + row) * LL + l0 + bl4];
            uint2 hi = make_uint2(bf2_hi(v.x, v.y), bf2_hi(v.z, v.w));
            uint2 lo = make_uint2(bf2_hi(bf_res(v.x), bf_res(v.y)),
                                  bf2_hi(bf_res(v.z), bf_res(v.w)));
            *(uint2*)&sBhi[row * BPITCH + bl4] = hi;
            *(uint2*)&sBlo[row * BPITCH + bl4] = lo;
        }
        __syncthreads();

        #pragma unroll
        for (int ks = 0; ks < 4; ks++) {
            const int kb = ks * 16;
            uint32_t ahi[2][4], alo[2][4], bhi[8][2], blo[8][2];

            #pragma unroll
            for (int mi = 0; mi < 2; mi++) {
                const uint32_t off =
                    (uint32_t)((a_row + mi * 16) * APITCH + kb + a_col) * 2;
                ldsm_x4(ahi[mi], uAhi + off);
                ldsm_x4(alo[mi], uAlo + off);
            }
            #pragma unroll
            for (int nq = 0; nq < 4; nq++) {
                const uint32_t off =
                    (uint32_t)((kb + b_row) * BPITCH + b_colb + nq * 16) * 2;
                uint32_t th[4], tl[4];
                ldsm_x4_t(th, uBhi + off);
                ldsm_x4_t(tl, uBlo + off);
                bhi[nq * 2 + 0][0] = th[0]; bhi[nq * 2 + 0][1] = th[1];
                bhi[nq * 2 + 1][0] = th[2]; bhi[nq * 2 + 1][1] = th[3];
                blo[nq * 2 + 0][0] = tl[0]; blo[nq * 2 + 0][1] = tl[1];
                blo[nq * 2 + 1][0] = tl[2]; blo[nq * 2 + 1][1] = tl[3];
            }

            #pragma unroll
            for (int mi = 0; mi < 2; mi++)
                #pragma unroll
                for (int ni = 0; ni < 8; ni++) {
                    mma_bf16(acc[mi][ni], ahi[mi], bhi[ni]);
                    mma_bf16(acc[mi][ni], ahi[mi], blo[ni]);
                    mma_bf16(acc[mi][ni], alo[mi], bhi[ni]);
                }
        }
    }

    const int r = lane >> 2;
    const int g = lane & 3;
    const size_t boff = (size_t)b * CC * LL;

    #pragma unroll
    for (int mi = 0; mi < 2; mi++) {
        const int o1 = o0 + wm * 32 + mi * 16 + r;
        const int o2 = o1 + 8;
        const float bv1 = __ldg(&bias[o1]);
        const float bv2 = __ldg(&bias[o2]);
        #pragma unroll
        for (int ni = 0; ni < 8; ni++) {
            const int l = l0 + wn * 64 + ni * 8 + g * 2;
            float2 v01 = make_float2(acc[mi][ni][0] + bv1, acc[mi][ni][1] + bv1);
            float2 v23 = make_float2(acc[mi][ni][2] + bv2, acc[mi][ni][3] + bv2);
            if (RELU) {
                v01.x = fmaxf(v01.x, 0.f); v01.y = fmaxf(v01.y, 0.f);
                v23.x = fmaxf(v23.x, 0.f); v23.y = fmaxf(v23.y, 0.f);
            }
            const size_t i1 = (size_t)o1 * LL + l;
            const size_t i2 = (size_t)o2 * LL + l;
            if (NADD >= 1) {
                float2 a1v = *(const float2*)&A1[boff + i1];
                float2 a2v = *(const float2*)&A1[boff + i2];
                v01.x += a1v.x; v01.y += a1v.y;
                v23.x += a2v.x; v23.y += a2v.y;
            }
            if (NADD >= 2) {
                float2 a1v = *(const float2*)&A2[boff + i1];
                float2 a2v = *(const float2*)&A2[boff + i2];
                v01.x += a1v.x; v01.y += a1v.y;
                v23.x += a2v.x; v23.y += a2v.y;
            }
            *(float2*)&Ob[i1] = v01;
            *(float2*)&Ob[i2] = v23;
        }
    }
}

// ---------------------------------------------------------------------------
// HMMA scores: S[bh,l,m] = (1/1024) * sum_{c<64} K[bh,c,l] * Q[bh,c,m]
// Output now stored as bf16 (scaled scores are ~1e-2; bf16 abs err ~1e-4).
// ---------------------------------------------------------------------------
#define SPITCH 136
#define SC_KHI 0
#define SC_KLO (64 * SPITCH)
#define SC_QHI (2 * 64 * SPITCH)
#define SC_QLO (3 * 64 * SPITCH)
#define SCORES_SMEM (4 * 64 * SPITCH * 2)   // 69,632 B

__global__ __launch_bounds__(256)
void scores_mma_kernel(const float* __restrict__ K, const float* __restrict__ Q,
                       __nv_bfloat16* __restrict__ S)
{
    extern __shared__ __align__(16) __nv_bfloat16 smem[];
    __nv_bfloat16* sKhi = smem + SC_KHI;
    __nv_bfloat16* sKlo = smem + SC_KLO;
    __nv_bfloat16* sQhi = smem + SC_QHI;
    __nv_bfloat16* sQlo = smem + SC_QLO;
    const uint32_t uKhi = smem_u32(sKhi);
    const uint32_t uKlo = smem_u32(sKlo);
    const uint32_t uQhi = smem_u32(sQhi);
    const uint32_t uQlo = smem_u32(sQlo);

    const int bh = blockIdx.z;
    const int b = bh >> 4, h = bh & 15;
    const int l0 = blockIdx.y * 128;
    const int m0 = blockIdx.x * 128;

    const size_t hoff = (size_t)b * CC * LL + (size_t)h * HD * LL;
    const float* Kb = K + hoff;
    const float* Qb = Q + hoff;
    __nv_bfloat16* Sb = S + (size_t)bh * LL * LL;

    const int tid  = threadIdx.x;
    const int wid  = tid >> 5;
    const int lane = tid & 31;
    const int wm   = wid & 3;
    const int wn   = wid >> 2;

    const int lr  = tid >> 5;
    const int lc4 = (tid & 31) * 4;

    #pragma unroll
    for (int p = 0; p < 8; p++) {
        const int row = lr + p * 8;
        float4 vk = *(const float4*)&Kb[(size_t)row * LL + l0 + lc4];
        float4 vq = *(const float4*)&Qb[(size_t)row * LL + m0 + lc4];
        *(uint2*)&sKhi[row * SPITCH + lc4] =
            make_uint2(bf2_hi(vk.x, vk.y), bf2_hi(vk.z, vk.w));
        *(uint2*)&sKlo[row * SPITCH + lc4] =
            make_uint2(bf2_hi(bf_res(vk.x), bf_res(vk.y)),
                       bf2_hi(bf_res(vk.z), bf_res(vk.w)));
        *(uint2*)&sQhi[row * SPITCH + lc4] =
            make_uint2(bf2_hi(vq.x, vq.y), bf2_hi(vq.z, vq.w));
        *(uint2*)&sQlo[row * SPITCH + lc4] =
            make_uint2(bf2_hi(bf_res(vq.x), bf_res(vq.y)),
                       bf2_hi(bf_res(vq.z), bf_res(vq.w)));
    }
    __syncthreads();

    const int a_krow = (lane & 7) + ((lane >> 4) & 1) * 8;
    const int a_mcol = wm * 32 + ((lane >> 3) & 1) * 8;
    const int b_krow = (lane & 15);
    const int b_mcol = wn * 64 + ((lane >> 4) & 1) * 8;

    float acc[2][8][4];
    #pragma unroll
    for (int mi = 0; mi < 2; mi++)
        #pragma unroll
        for (int ni = 0; ni < 8; ni++)
            #pragma unroll
            for (int q = 0; q < 4; q++) acc[mi][ni][q] = 0.0f;

    #pragma unroll
    for (int ks = 0; ks < 4; ks++) {
        const int kb = ks * 16;
        uint32_t ahi[2][4], alo[2][4], bhi[8][2], blo[8][2];

        #pragma unroll
        for (int mi = 0; mi < 2; mi++) {
            const uint32_t off =
                (uint32_t)((kb + a_krow) * SPITCH + a_mcol + mi * 16) * 2;
            ldsm_x4_t(ahi[mi], uKhi + off);
            ldsm_x4_t(alo[mi], uKlo + off);
        }
        #pragma unroll
        for (int nq = 0; nq < 4; nq++) {
            const uint32_t off =
                (uint32_t)((kb + b_krow) * SPITCH + b_mcol + nq * 16) * 2;
            uint32_t th[4], tl[4];
            ldsm_x4_t(th, uQhi + off);
            ldsm_x4_t(tl, uQlo + off);
            bhi[nq * 2 + 0][0] = th[0]; bhi[nq * 2 + 0][1] = th[1];
            bhi[nq * 2 + 1][0] = th[2]; bhi[nq * 2 + 1][1] = th[3];
            blo[nq * 2 + 0][0] = tl[0]; blo[nq * 2 + 0][1] = tl[1];
            blo[nq * 2 + 1][0] = tl[2]; blo[nq * 2 + 1][1] = tl[3];
        }

        #pragma unroll
        for (int mi = 0; mi < 2; mi++)
            #pragma unroll
            for (int ni = 0; ni < 8; ni++) {
                mma_bf16(acc[mi][ni], ahi[mi], bhi[ni]);
                mma_bf16(acc[mi][ni], ahi[mi], blo[ni]);
                mma_bf16(acc[mi][ni], alo[mi], bhi[ni]);
            }
    }

    const int r = lane >> 2;
    const int g = lane & 3;
    const float scale = 1.0f / 1024.0f;

    #pragma unroll
    for (int mi = 0; mi < 2; mi++) {
        const int l1 = l0 + wm * 32 + mi * 16 + r;
        const int l2 = l1 + 8;
        #pragma unroll
        for (int ni = 0; ni < 8; ni++) {
            const int m = m0 + wn * 64 + ni * 8 + g * 2;
            const uint32_t p01 = bf2_hi(acc[mi][ni][0] * scale, acc[mi][ni][1] * scale);
            const uint32_t p23 = bf2_hi(acc[mi][ni][2] * scale, acc[mi][ni][3] * scale);
            *(uint32_t*)&Sb[(size_t)l1 * LL + m] = p01;
            *(uint32_t*)&Sb[(size_t)l2 * LL + m] = p23;
        }
    }
}

// ---------------------------------------------------------------------------
// softmax over last axis (2048), bf16 in/out, one block (256 thr) per row.
// Each thread owns 8 elements (one uint4).
// ---------------------------------------------------------------------------
__device__ __forceinline__ float warp_rmax(float v) {
    #pragma unroll
    for (int o = 16; o > 0; o >>= 1) v = fmaxf(v, __shfl_xor_sync(0xffffffffu, v, o));
    return v;
}
__device__ __forceinline__ float warp_rsum(float v) {
    #pragma unroll
    for (int o = 16; o > 0; o >>= 1) v += __shfl_xor_sync(0xffffffffu, v, o);
    return v;
}

__global__ __launch_bounds__(256)
void softmax_bf16_kernel(__nv_bfloat16* __restrict__ S)
{
    const size_t row = blockIdx.x;
    __nv_bfloat16* p = S + row * LL;
    const int tid = threadIdx.x;
    const int lane = tid & 31, wid = tid >> 5;

    uint4 raw = reinterpret_cast<uint4*>(p)[tid];
    float f[8];
    {
        float2 t;
        t = __bfloat1622float2(*(__nv_bfloat162*)&raw.x); f[0] = t.x; f[1] = t.y;
        t = __bfloat1622float2(*(__nv_bfloat162*)&raw.y); f[2] = t.x; f[3] = t.y;
        t = __bfloat1622float2(*(__nv_bfloat162*)&raw.z); f[4] = t.x; f[5] = t.y;
        t = __bfloat1622float2(*(__nv_bfloat162*)&raw.w); f[6] = t.x; f[7] = t.y;
    }

    float m = f[0];
    #pragma unroll
    for (int i = 1; i < 8; i++) m = fmaxf(m, f[i]);

    __shared__ float sred[8];
    __shared__ float sbroad;

    m = warp_rmax(m);
    if (lane == 0) sred[wid] = m;
    __syncthreads();
    if (tid == 0) {
        float t = sred[0];
        #pragma unroll
        for (int i = 1; i < 8; i++) t = fmaxf(t, sred[i]);
        sbroad = t;
    }
    __syncthreads();
    const float mx = sbroad;
    __syncthreads();

    float s = 0.0f;
    #pragma unroll
    for (int i = 0; i < 8; i++) { f[i] = __expf(f[i] - mx); s += f[i]; }

    s = warp_rsum(s);
    if (lane == 0) sred[wid] = s;
    __syncthreads();
    if (tid == 0) {
        float t = 0.0f;
        #pragma unroll
        for (int i = 0; i < 8; i++) t += sred[i];
        sbroad = t;
    }
    __syncthreads();
    const float inv = 1.0f / sbroad;

    raw.x = bf2_hi(f[0] * inv, f[1] * inv);
    raw.y = bf2_hi(f[2] * inv, f[3] * inv);
    raw.z = bf2_hi(f[4] * inv, f[5] * inv);
    raw.w = bf2_hi(f[6] * inv, f[7] * inv);
    reinterpret_cast<uint4*>(p)[tid] = raw;
}

// ---------------------------------------------------------------------------
// HMMA AV: O[bh,c,m] = sum_l X[bh,c,l] * P[bh,l,m]   (P in bf16, no split)
// Block 64(c) x 128(m), 256 thr (8 warps, warp tile 16x64). l chunks of 64.
// A = X rows split hi/lo (plain ldmatrix); B = P rows raw bf16 (trans).
// ---------------------------------------------------------------------------
#define XP 72
#define PP 136
#define AV_XHI 0
#define AV_XLO (64 * XP)
#define AV_P   (2 * 64 * XP)
#define AV_SMEM ((2 * 64 * XP + 64 * PP) * 2)   // 35,840 B

__global__ __launch_bounds__(256)
void av_mma_kernel(const float* __restrict__ X,
                   const __nv_bfloat16* __restrict__ Pm,
                   float* __restrict__ O)
{
    extern __shared__ __align__(16) __nv_bfloat16 smem[];
    __nv_bfloat16* sXhi = smem + AV_XHI;
    __nv_bfloat16* sXlo = smem + AV_XLO;
    __nv_bfloat16* sP   = smem + AV_P;
    const uint32_t uXhi = smem_u32(sXhi);
    const uint32_t uXlo = smem_u32(sXlo);
    const uint32_t uP   = smem_u32(sP);

    const int bh = blockIdx.y;
    const int b = bh >> 4, h = bh & 15;
    const int m0 = blockIdx.x * 128;

    const size_t hoff = (size_t)b * CC * LL + (size_t)h * HD * LL;
    const float* Xb = X + hoff;
    const __nv_bfloat16* Ab = Pm + (size_t)bh * LL * LL;
    float* Ob = O + hoff;

    const int tid  = threadIdx.x;
    const int wid  = tid >> 5;
    const int lane = tid & 31;
    const int wm   = wid & 3;          // c group of 16
    const int wn   = wid >> 2;         // m group of 64

    // X loader: 64 rows x 64 cols fp32
    const int xr  = tid >> 4;          // 0..15
    const int xc4 = (tid & 15) * 4;
    // P loader: 64 rows x 128 cols bf16, uint4 = 8 elems
    const int prr = tid >> 4;          // 0..15
    const int pc8 = (tid & 15) * 8;

    const int a_row = wm * 16 + (lane & 15);
    const int a_col = ((lane >> 4) & 1) * 8;
    const int b_krow = (lane & 15);
    const int b_mcol = wn * 64 + ((lane >> 4) & 1) * 8;

    float acc[8][4];
    #pragma unroll
    for (int ni = 0; ni < 8; ni++)
        #pragma unroll
        for (int q = 0; q < 4; q++) acc[ni][q] = 0.0f;

    for (int l0 = 0; l0 < LL; l0 += 64) {
        if (l0) __syncthreads();

        #pragma unroll
        for (int p = 0; p < 4; p++) {
            const int row = xr + p * 16;      // c
            float4 v = *(const float4*)&Xb[(size_t)row * LL + l0 + xc4];
            *(uint2*)&sXhi[row * XP + xc4] =
                make_uint2(bf2_hi(v.x, v.y), bf2_hi(v.z, v.w));
            *(uint2*)&sXlo[row * XP + xc4] =
                make_uint2(bf2_hi(bf_res(v.x), bf_res(v.y)),
                           bf2_hi(bf_res(v.z), bf_res(v.w)));
        }
        #pragma unroll
        for (int p = 0; p < 4; p++) {
            const int row = prr + p * 16;     // l within chunk
            *(uint4*)&sP[row * PP + pc8] =
                *(const uint4*)&Ab[(size_t)(l0 + row) * LL + m0 + pc8];
        }
        __syncthreads();

        #pragma unroll
        for (int ks = 0; ks < 4; ks++) {
            const int kb = ks * 16;
            uint32_t ahi[4], alo[4], bp[8][2];

            {
                const uint32_t off = (uint32_t)(a_row * XP + kb + a_col) * 2;
                ldsm_x4(ahi, uXhi + off);
                ldsm_x4(alo, uXlo + off);
            }
            #pragma unroll
            for (int nq = 0; nq < 4; nq++) {
                const uint32_t off =
                    (uint32_t)((kb + b_krow) * PP + b_mcol + nq * 16) * 2;
                uint32_t th[4];
                ldsm_x4_t(th, uP + off);
                bp[nq * 2 + 0][0] = th[0]; bp[nq * 2 + 0][1] = th[1];
                bp[nq * 2 + 1][0] = th[2]; bp[nq * 2 + 1][1] = th[3];
            }

            #pragma unroll
            for (int ni = 0; ni < 8; ni++) {
                mma_bf16(acc[ni], ahi, bp[ni]);
                mma_bf16(acc[ni], alo, bp[ni]);
            }
        }
    }

    const int r = lane >> 2;
    const int g = lane & 3;
    const int c1 = wm * 16 + r;
    const int c2 = c1 + 8;

    #pragma unroll
    for (int ni = 0; ni < 8; ni++) {
        const int m = m0 + wn * 64 + ni * 8 + g * 2;
        *(float2*)&Ob[(size_t)c1 * LL + m] = make_float2(acc[ni][0], acc[ni][1]);
        *(float2*)&Ob[(size_t)c2 * LL + m] = make_float2(acc[ni][2], acc[ni][3]);
    }
}

// ---------------------------------------------------------------------------
extern "C" void kernel_launch(void* const* d_in, const int* in_sizes, int n_in,
                              void* d_out, int out_size)
{
    const float* x   = (const float*)d_in[0];
    const float* kw  = (const float*)d_in[1];
    const float* kb  = (const float*)d_in[2];
    const float* qw  = (const float*)d_in[3];
    const float* qb  = (const float*)d_in[4];
    const float* pw  = (const float*)d_in[5];
    const float* pb  = (const float*)d_in[6];
    const float* c1w = (const float*)d_in[7];
    const float* c1b = (const float*)d_in[8];
    const float* c2w = (const float*)d_in[9];
    const float* c2b = (const float*)d_in[10];
    float* out = (float*)d_out;

    float *gK, *gQ, *gAO, *gY, *gT;
    __nv_bfloat16* gS;
    cudaGetSymbolAddress((void**)&gK,  g_K);
    cudaGetSymbolAddress((void**)&gQ,  g_Q);
    cudaGetSymbolAddress((void**)&gS,  g_S);
    cudaGetSymbolAddress((void**)&gAO, g_AO);
    cudaGetSymbolAddress((void**)&gY,  g_Y);
    cudaGetSymbolAddress((void**)&gT,  g_T);

    static bool attr_done = false;
    if (!attr_done) {
        cudaFuncSetAttribute(scores_mma_kernel,
                             cudaFuncAttributeMaxDynamicSharedMemorySize, SCORES_SMEM);
        cudaFuncSetAttribute(av_mma_kernel,
                             cudaFuncAttributeMaxDynamicSharedMemorySize, AV_SMEM);
        cudaFuncSetAttribute(conv_mma_kernel<false, 0>,
                             cudaFuncAttributeMaxDynamicSharedMemorySize, CONV_SMEM);
        cudaFuncSetAttribute(conv_mma_kernel<false, 1>,
                             cudaFuncAttributeMaxDynamicSharedMemorySize, CONV_SMEM);
        cudaFuncSetAttribute(conv_mma_kernel<false, 2>,
                             cudaFuncAttributeMaxDynamicSharedMemorySize, CONV_SMEM);
        cudaFuncSetAttribute(conv_mma_kernel<true, 0>,
                             cudaFuncAttributeMaxDynamicSharedMemorySize, CONV_SMEM);
        attr_done = true;
    }

    dim3 cgrid(LL / 128, CC / 128, BB);   // (16,8,2)

    // K and Q projections (HMMA, bf16 split)
    conv_mma_kernel<false, 0><<<cgrid, 256, CONV_SMEM>>>(kw, kb, x, gK, nullptr, nullptr);
    conv_mma_kernel<false, 0><<<cgrid, 256, CONV_SMEM>>>(qw, qb, x, gQ, nullptr, nullptr);

    // scores (HMMA, bf16 out) -> softmax (bf16) -> AV (HMMA, bf16 P)
    scores_mma_kernel<<<dim3(LL / 128, LL / 128, NBH), 256, SCORES_SMEM>>>(gK, gQ, gS);
    softmax_bf16_kernel<<<(unsigned)SROWS, 256>>>(gS);
    av_mma_kernel<<<dim3(LL / 128, NBH), 256, AV_SMEM>>>(x, gS, gAO);

    // y = pconv(attn_out) + x
    conv_mma_kernel<false, 1><<<cgrid, 256, CONV_SMEM>>>(pw, pb, gAO, gY, x, nullptr);
    // t = relu(c1(y))
    conv_mma_kernel<true, 0><<<cgrid, 256, CONV_SMEM>>>(c1w, c1b, gY, gT, nullptr, nullptr);
    // out = c2(t) + y + x
    conv_mma_kernel<false, 2><<<cgrid, 256, CONV_SMEM>>>(c2w, c2b, gT, out, gY, x);
}

// round 9
// speedup vs baseline: 4.1410x; 1.0637x over previous
#include <cuda_runtime.h>
#include <cuda_bf16.h>
#include <cstdint>

// Problem constants
#define BB 2
#define CC 1024
#define LL 2048
#define HH 16
#define HD 64
#define BCL (BB*CC*LL)               // 4,194,304 elems
#define NBH (BB*HH)                  // 32
#define SROWS ((size_t)NBH * LL)     // 65536
#define SELEMS (SROWS * LL)          // 134,217,728 elems (256 MB bf16)
#define WELEMS (CC*CC)               // 1,048,576 per weight

// Scratch (device globals — runtime allocation is forbidden)
__device__ __nv_bfloat16 g_XH[BCL], g_XL[BCL];        // x split
__device__ __nv_bfloat16 g_KH[BCL], g_KL[BCL];        // K proj split
__device__ __nv_bfloat16 g_QH[BCL], g_QL[BCL];        // Q proj split
__device__ __nv_bfloat16 g_AH[BCL], g_AL[BCL];        // attn out split
__device__ float         g_Y [BCL];                   // y fp32 (residual)
__device__ __nv_bfloat16 g_YH[BCL], g_YL[BCL];        // y split
__device__ __nv_bfloat16 g_TH[BCL], g_TL[BCL];        // relu(c1(y)) split
__device__ __nv_bfloat16 g_S [SELEMS];                // scores/probs bf16
__device__ __nv_bfloat16 g_WH[5*WELEMS], g_WL[5*WELEMS];  // weights split

// ---------------------------------------------------------------------------
// helpers
// ---------------------------------------------------------------------------
__device__ __forceinline__ uint32_t smem_u32(const void* p) {
    uint32_t a;
    asm("{ .reg .u64 t; cvta.to.shared.u64 t, %1; cvt.u32.u64 %0, t; }"
        : "=r"(a) : "l"(p));
    return a;
}
__device__ __forceinline__ uint32_t bf2_hi(float a, float b) {
    __nv_bfloat162 t = __floats2bfloat162_rn(a, b);
    return *reinterpret_cast<uint32_t*>(&t);
}
__device__ __forceinline__ float bf_res(float v) {   // v - bf16(v)
    __nv_bfloat16 h = __float2bfloat16(v);
    return v - __bfloat162float(h);
}

__device__ __forceinline__ void ldsm_x4(uint32_t r[4], uint32_t addr) {
    asm volatile("ldmatrix.sync.aligned.m8n8.x4.shared.b16 {%0,%1,%2,%3}, [%4];"
                 : "=r"(r[0]), "=r"(r[1]), "=r"(r[2]), "=r"(r[3]) : "r"(addr));
}
__device__ __forceinline__ void ldsm_x4_t(uint32_t r[4], uint32_t addr) {
    asm volatile("ldmatrix.sync.aligned.m8n8.x4.trans.shared.b16 {%0,%1,%2,%3}, [%4];"
                 : "=r"(r[0]), "=r"(r[1]), "=r"(r[2]), "=r"(r[3]) : "r"(addr));
}
__device__ __forceinline__ void mma_bf16(float c[4], const uint32_t a[4],
                                         const uint32_t b[2]) {
    asm volatile("mma.sync.aligned.m16n8k16.row.col.f32.bf16.bf16.f32 "
                 "{%0,%1,%2,%3}, {%4,%5,%6,%7}, {%8,%9}, {%0,%1,%2,%3};"
                 : "+f"(c[0]), "+f"(c[1]), "+f"(c[2]), "+f"(c[3])
                 : "r"(a[0]), "r"(a[1]), "r"(a[2]), "r"(a[3]),
                   "r"(b[0]), "r"(b[1]));
}

// ---------------------------------------------------------------------------
// split: fp32 -> (hi, lo) bf16 arrays.  n must be /4; 1 float4 per thread.
// ---------------------------------------------------------------------------
__global__ __launch_bounds__(256)
void split_kernel(const float* __restrict__ in, __nv_bfloat16* __restrict__ hi,
                  __nv_bfloat16* __restrict__ lo)
{
    const unsigned i = blockIdx.x * 256u + threadIdx.x;
    float4 v = reinterpret_cast<const float4*>(in)[i];
    uint2 h = make_uint2(bf2_hi(v.x, v.y), bf2_hi(v.z, v.w));
    uint2 l = make_uint2(bf2_hi(bf_res(v.x), bf_res(v.y)),
                         bf2_hi(bf_res(v.z), bf_res(v.w)));
    reinterpret_cast<uint2*>(hi)[i] = h;
    reinterpret_cast<uint2*>(lo)[i] = l;
}

// ---------------------------------------------------------------------------
// HMMA conv1x1 on pre-split operands.
// Out[b,o,l] = sum_c W[o,c]*X[b,c,l] + bias[o]  (+A1 +A2, relu opt)
// OMODE: 0 = write (OH,OL) split only; 1 = write fp32 Out AND split; 2 = fp32.
// ---------------------------------------------------------------------------
#define APITCH 72    // bf16 per A row (144 B)
#define BPITCH 136   // bf16 per B row (272 B)
#define SM_AHI 0
#define SM_ALO (128 * APITCH)
#define SM_BHI (2 * 128 * APITCH)
#define SM_BLO (2 * 128 * APITCH + 64 * BPITCH)
#define CONV_SMEM ((2 * 128 * APITCH + 2 * 64 * BPITCH) * 2)   // 71,680 B

template<bool RELU, int NADD, int OMODE>
__global__ __launch_bounds__(256)
void conv_mma_kernel(const __nv_bfloat16* __restrict__ WH,
                     const __nv_bfloat16* __restrict__ WL,
                     const float* __restrict__ bias,
                     const __nv_bfloat16* __restrict__ BH,
                     const __nv_bfloat16* __restrict__ BL,
                     float* __restrict__ Out,
                     __nv_bfloat16* __restrict__ OH,
                     __nv_bfloat16* __restrict__ OL,
                     const float* __restrict__ A1,
                     const float* __restrict__ A2)
{
    extern __shared__ __align__(16) __nv_bfloat16 smem[];
    __nv_bfloat16* sAhi = smem + SM_AHI;
    __nv_bfloat16* sAlo = smem + SM_ALO;
    __nv_bfloat16* sBhi = smem + SM_BHI;
    __nv_bfloat16* sBlo = smem + SM_BLO;
    const uint32_t uAhi = smem_u32(sAhi);
    const uint32_t uAlo = smem_u32(sAlo);
    const uint32_t uBhi = smem_u32(sBhi);
    const uint32_t uBlo = smem_u32(sBlo);

    const int b  = blockIdx.z;
    const int o0 = blockIdx.y * 128;
    const int l0 = blockIdx.x * 128;
    const size_t boff = (size_t)b * CC * LL;

    const int tid  = threadIdx.x;
    const int wid  = tid >> 5;
    const int lane = tid & 31;
    const int wm   = wid & 3;
    const int wn   = wid >> 2;

    const int ar  = tid >> 4;          // A loader: row group 0..15
    const int ac4 = (tid & 15) * 4;
    const int bc  = tid >> 5;          // B loader: row group 0..7
    const int bl4 = (tid & 31) * 4;

    const int a_row = wm * 32 + (lane & 15);
    const int a_col = ((lane >> 4) & 1) * 8;
    const int b_row = (lane & 15);
    const int b_colb = wn * 64 + ((lane >> 4) & 1) * 8;

    float acc[2][8][4];
    #pragma unroll
    for (int mi = 0; mi < 2; mi++)
        #pragma unroll
        for (int ni = 0; ni < 8; ni++)
            #pragma unroll
            for (int q = 0; q < 4; q++) acc[mi][ni][q] = 0.0f;

    for (int ci = 0; ci < CC / 64; ci++) {
        const int c0 = ci * 64;
        if (ci) __syncthreads();

        // A tile: pre-split W, pure copy
        #pragma unroll
        for (int p = 0; p < 8; p++) {
            const int row = ar + p * 16;
            const size_t g = (size_t)(o0 + row) * CC + c0 + ac4;
            *(uint2*)&sAhi[row * APITCH + ac4] = *(const uint2*)&WH[g];
            *(uint2*)&sAlo[row * APITCH + ac4] = *(const uint2*)&WL[g];
        }
        // B tile: pre-split activations, pure copy
        #pragma unroll
        for (int p = 0; p < 8; p++) {
            const int row = bc + p * 8;
            const size_t g = boff + (size_t)(c0 + row) * LL + l0 + bl4;
            *(uint2*)&sBhi[row * BPITCH + bl4] = *(const uint2*)&BH[g];
            *(uint2*)&sBlo[row * BPITCH + bl4] = *(const uint2*)&BL[g];
        }
        __syncthreads();

        #pragma unroll
        for (int ks = 0; ks < 4; ks++) {
            const int kb = ks * 16;
            uint32_t ahi[2][4], alo[2][4], bhi[8][2], blo[8][2];

            #pragma unroll
            for (int mi = 0; mi < 2; mi++) {
                const uint32_t off =
                    (uint32_t)((a_row + mi * 16) * APITCH + kb + a_col) * 2;
                ldsm_x4(ahi[mi], uAhi + off);
                ldsm_x4(alo[mi], uAlo + off);
            }
            #pragma unroll
            for (int nq = 0; nq < 4; nq++) {
                const uint32_t off =
                    (uint32_t)((kb + b_row) * BPITCH + b_colb + nq * 16) * 2;
                uint32_t th[4], tl[4];
                ldsm_x4_t(th, uBhi + off);
                ldsm_x4_t(tl, uBlo + off);
                bhi[nq * 2 + 0][0] = th[0]; bhi[nq * 2 + 0][1] = th[1];
                bhi[nq * 2 + 1][0] = th[2]; bhi[nq * 2 + 1][1] = th[3];
                blo[nq * 2 + 0][0] = tl[0]; blo[nq * 2 + 0][1] = tl[1];
                blo[nq * 2 + 1][0] = tl[2]; blo[nq * 2 + 1][1] = tl[3];
            }

            #pragma unroll
            for (int mi = 0; mi < 2; mi++)
                #pragma unroll
                for (int ni = 0; ni < 8; ni++) {
                    mma_bf16(acc[mi][ni], ahi[mi], bhi[ni]);
                    mma_bf16(acc[mi][ni], ahi[mi], blo[ni]);
                    mma_bf16(acc[mi][ni], alo[mi], bhi[ni]);
                }
        }
    }

    const int r = lane >> 2;
    const int g = lane & 3;

    #pragma unroll
    for (int mi = 0; mi < 2; mi++) {
        const int o1 = o0 + wm * 32 + mi * 16 + r;
        const int o2 = o1 + 8;
        const float bv1 = __ldg(&bias[o1]);
        const float bv2 = __ldg(&bias[o2]);
        #pragma unroll
        for (int ni = 0; ni < 8; ni++) {
            const int l = l0 + wn * 64 + ni * 8 + g * 2;
            float2 v01 = make_float2(acc[mi][ni][0] + bv1, acc[mi][ni][1] + bv1);
            float2 v23 = make_float2(acc[mi][ni][2] + bv2, acc[mi][ni][3] + bv2);
            if (RELU) {
                v01.x = fmaxf(v01.x, 0.f); v01.y = fmaxf(v01.y, 0.f);
                v23.x = fmaxf(v23.x, 0.f); v23.y = fmaxf(v23.y, 0.f);
            }
            const size_t i1 = boff + (size_t)o1 * LL + l;
            const size_t i2 = boff + (size_t)o2 * LL + l;
            if (NADD >= 1) {
                float2 a1v = *(const float2*)&A1[i1];
                float2 a2v = *(const float2*)&A1[i2];
                v01.x += a1v.x; v01.y += a1v.y;
                v23.x += a2v.x; v23.y += a2v.y;
            }
            if (NADD >= 2) {
                float2 a1v = *(const float2*)&A2[i1];
                float2 a2v = *(const float2*)&A2[i2];
                v01.x += a1v.x; v01.y += a1v.y;
                v23.x += a2v.x; v23.y += a2v.y;
            }
            if (OMODE >= 1) {
                *(float2*)&Out[i1] = v01;
                *(float2*)&Out[i2] = v23;
            }
            if (OMODE <= 1) {
                *(uint32_t*)&OH[i1] = bf2_hi(v01.x, v01.y);
                *(uint32_t*)&OH[i2] = bf2_hi(v23.x, v23.y);
                *(uint32_t*)&OL[i1] = bf2_hi(bf_res(v01.x), bf_res(v01.y));
                *(uint32_t*)&OL[i2] = bf2_hi(bf_res(v23.x), bf_res(v23.y));
            }
        }
    }
}

// ---------------------------------------------------------------------------
// HMMA scores: S[bh,l,m] = (1/1024) * sum_{c<64} K[c,l]*Q[c,m], bf16 out.
// K/Q pre-split in gmem; loaders are pure copies.
// ---------------------------------------------------------------------------
#define SPITCH 136
#define SC_KHI 0
#define SC_KLO (64 * SPITCH)
#define SC_QHI (2 * 64 * SPITCH)
#define SC_QLO (3 * 64 * SPITCH)
#define SCORES_SMEM (4 * 64 * SPITCH * 2)   // 69,632 B

__global__ __launch_bounds__(256)
void scores_mma_kernel(const __nv_bfloat16* __restrict__ KH,
                       const __nv_bfloat16* __restrict__ KL,
                       const __nv_bfloat16* __restrict__ QH,
                       const __nv_bfloat16* __restrict__ QL,
                       __nv_bfloat16* __restrict__ S)
{
    extern __shared__ __align__(16) __nv_bfloat16 smem[];
    __nv_bfloat16* sKhi = smem + SC_KHI;
    __nv_bfloat16* sKlo = smem + SC_KLO;
    __nv_bfloat16* sQhi = smem + SC_QHI;
    __nv_bfloat16* sQlo = smem + SC_QLO;
    const uint32_t uKhi = smem_u32(sKhi);
    const uint32_t uKlo = smem_u32(sKlo);
    const uint32_t uQhi = smem_u32(sQhi);
    const uint32_t uQlo = smem_u32(sQlo);

    const int bh = blockIdx.z;
    const int b = bh >> 4, h = bh & 15;
    const int l0 = blockIdx.y * 128;
    const int m0 = blockIdx.x * 128;

    const size_t hoff = (size_t)b * CC * LL + (size_t)h * HD * LL;
    __nv_bfloat16* Sb = S + (size_t)bh * LL * LL;

    const int tid  = threadIdx.x;
    const int wid  = tid >> 5;
    const int lane = tid & 31;
    const int wm   = wid & 3;
    const int wn   = wid >> 2;

    const int lr  = tid >> 5;
    const int lc4 = (tid & 31) * 4;

    #pragma unroll
    for (int p = 0; p < 8; p++) {
        const int row = lr + p * 8;
        const size_t gk = hoff + (size_t)row * LL + l0 + lc4;
        const size_t gq = hoff + (size_t)row * LL + m0 + lc4;
        *(uint2*)&sKhi[row * SPITCH + lc4] = *(const uint2*)&KH[gk];
        *(uint2*)&sKlo[row * SPITCH + lc4] = *(const uint2*)&KL[gk];
        *(uint2*)&sQhi[row * SPITCH + lc4] = *(const uint2*)&QH[gq];
        *(uint2*)&sQlo[row * SPITCH + lc4] = *(const uint2*)&QL[gq];
    }
    __syncthreads();

    const int a_krow = (lane & 7) + ((lane >> 4) & 1) * 8;
    const int a_mcol = wm * 32 + ((lane >> 3) & 1) * 8;
    const int b_krow = (lane & 15);
    const int b_mcol = wn * 64 + ((lane >> 4) & 1) * 8;

    float acc[2][8][4];
    #pragma unroll
    for (int mi = 0; mi < 2; mi++)
        #pragma unroll
        for (int ni = 0; ni < 8; ni++)
            #pragma unroll
            for (int q = 0; q < 4; q++) acc[mi][ni][q] = 0.0f;

    #pragma unroll
    for (int ks = 0; ks < 4; ks++) {
        const int kb = ks * 16;
        uint32_t ahi[2][4], alo[2][4], bhi[8][2], blo[8][2];

        #pragma unroll
        for (int mi = 0; mi < 2; mi++) {
            const uint32_t off =
                (uint32_t)((kb + a_krow) * SPITCH + a_mcol + mi * 16) * 2;
            ldsm_x4_t(ahi[mi], uKhi + off);
            ldsm_x4_t(alo[mi], uKlo + off);
        }
        #pragma unroll
        for (int nq = 0; nq < 4; nq++) {
            const uint32_t off =
                (uint32_t)((kb + b_krow) * SPITCH + b_mcol + nq * 16) * 2;
            uint32_t th[4], tl[4];
            ldsm_x4_t(th, uQhi + off);
            ldsm_x4_t(tl, uQlo + off);
            bhi[nq * 2 + 0][0] = th[0]; bhi[nq * 2 + 0][1] = th[1];
            bhi[nq * 2 + 1][0] = th[2]; bhi[nq * 2 + 1][1] = th[3];
            blo[nq * 2 + 0][0] = tl[0]; blo[nq * 2 + 0][1] = tl[1];
            blo[nq * 2 + 1][0] = tl[2]; blo[nq * 2 + 1][1] = tl[3];
        }

        #pragma unroll
        for (int mi = 0; mi < 2; mi++)
            #pragma unroll
            for (int ni = 0; ni < 8; ni++) {
                mma_bf16(acc[mi][ni], ahi[mi], bhi[ni]);
                mma_bf16(acc[mi][ni], ahi[mi], blo[ni]);
                mma_bf16(acc[mi][ni], alo[mi], bhi[ni]);
            }
    }

    const int r = lane >> 2;
    const int g = lane & 3;
    const float scale = 1.0f / 1024.0f;

    #pragma unroll
    for (int mi = 0; mi < 2; mi++) {
        const int l1 = l0 + wm * 32 + mi * 16 + r;
        const int l2 = l1 + 8;
        #pragma unroll
        for (int ni = 0; ni < 8; ni++) {
            const int m = m0 + wn * 64 + ni * 8 + g * 2;
            *(uint32_t*)&Sb[(size_t)l1 * LL + m] =
                bf2_hi(acc[mi][ni][0] * scale, acc[mi][ni][1] * scale);
            *(uint32_t*)&Sb[(size_t)l2 * LL + m] =
                bf2_hi(acc[mi][ni][2] * scale, acc[mi][ni][3] * scale);
        }
    }
}

// ---------------------------------------------------------------------------
// softmax over last axis (2048), bf16 in/out, one block (256 thr) per row.
// ---------------------------------------------------------------------------
__device__ __forceinline__ float warp_rmax(float v) {
    #pragma unroll
    for (int o = 16; o > 0; o >>= 1) v = fmaxf(v, __shfl_xor_sync(0xffffffffu, v, o));
    return v;
}
__device__ __forceinline__ float warp_rsum(float v) {
    #pragma unroll
    for (int o = 16; o > 0; o >>= 1) v += __shfl_xor_sync(0xffffffffu, v, o);
    return v;
}

__global__ __launch_bounds__(256)
void softmax_bf16_kernel(__nv_bfloat16* __restrict__ S)
{
    const size_t row = blockIdx.x;
    __nv_bfloat16* p = S + row * LL;
    const int tid = threadIdx.x;
    const int lane = tid & 31, wid = tid >> 5;

    uint4 raw = reinterpret_cast<uint4*>(p)[tid];
    float f[8];
    {
        float2 t;
        t = __bfloat1622float2(*(__nv_bfloat162*)&raw.x); f[0] = t.x; f[1] = t.y;
        t = __bfloat1622float2(*(__nv_bfloat162*)&raw.y); f[2] = t.x; f[3] = t.y;
        t = __bfloat1622float2(*(__nv_bfloat162*)&raw.z); f[4] = t.x; f[5] = t.y;
        t = __bfloat1622float2(*(__nv_bfloat162*)&raw.w); f[6] = t.x; f[7] = t.y;
    }

    float m = f[0];
    #pragma unroll
    for (int i = 1; i < 8; i++) m = fmaxf(m, f[i]);

    __shared__ float sred[8];
    __shared__ float sbroad;

    m = warp_rmax(m);
    if (lane == 0) sred[wid] = m;
    __syncthreads();
    if (tid == 0) {
        float t = sred[0];
        #pragma unroll
        for (int i = 1; i < 8; i++) t = fmaxf(t, sred[i]);
        sbroad = t;
    }
    __syncthreads();
    const float mx = sbroad;
    __syncthreads();

    float s = 0.0f;
    #pragma unroll
    for (int i = 0; i < 8; i++) { f[i] = __expf(f[i] - mx); s += f[i]; }

    s = warp_rsum(s);
    if (lane == 0) sred[wid] = s;
    __syncthreads();
    if (tid == 0) {
        float t = 0.0f;
        #pragma unroll
        for (int i = 0; i < 8; i++) t += sred[i];
        sbroad = t;
    }
    __syncthreads();
    const float inv = 1.0f / sbroad;

    raw.x = bf2_hi(f[0] * inv, f[1] * inv);
    raw.y = bf2_hi(f[2] * inv, f[3] * inv);
    raw.z = bf2_hi(f[4] * inv, f[5] * inv);
    raw.w = bf2_hi(f[6] * inv, f[7] * inv);
    reinterpret_cast<uint4*>(p)[tid] = raw;
}

// ---------------------------------------------------------------------------
// HMMA AV: O[bh,c,m] = sum_l X[c,l] * P[l,m]; X pre-split, P bf16.
// Output written as split (OH, OL) only — sole consumer is pconv.
// ---------------------------------------------------------------------------
#define XP 72
#define PP 136
#define AV_XHI 0
#define AV_XLO (64 * XP)
#define AV_P   (2 * 64 * XP)
#define AV_SMEM ((2 * 64 * XP + 64 * PP) * 2)   // 35,840 B

__global__ __launch_bounds__(256)
void av_mma_kernel(const __nv_bfloat16* __restrict__ XH,
                   const __nv_bfloat16* __restrict__ XL,
                   const __nv_bfloat16* __restrict__ Pm,
                   __nv_bfloat16* __restrict__ OH,
                   __nv_bfloat16* __restrict__ OL)
{
    extern __shared__ __align__(16) __nv_bfloat16 smem[];
    __nv_bfloat16* sXhi = smem + AV_XHI;
    __nv_bfloat16* sXlo = smem + AV_XLO;
    __nv_bfloat16* sP   = smem + AV_P;
    const uint32_t uXhi = smem_u32(sXhi);
    const uint32_t uXlo = smem_u32(sXlo);
    const uint32_t uP   = smem_u32(sP);

    const int bh = blockIdx.y;
    const int b = bh >> 4, h = bh & 15;
    const int m0 = blockIdx.x * 128;

    const size_t hoff = (size_t)b * CC * LL + (size_t)h * HD * LL;
    const __nv_bfloat16* Ab = Pm + (size_t)bh * LL * LL;

    const int tid  = threadIdx.x;
    const int wid  = tid >> 5;
    const int lane = tid & 31;
    const int wm   = wid & 3;
    const int wn   = wid >> 2;

    const int xr  = tid >> 4;          // 0..15
    const int xc4 = (tid & 15) * 4;
    const int prr = tid >> 4;          // 0..15
    const int pc8 = (tid & 15) * 8;

    const int a_row = wm * 16 + (lane & 15);
    const int a_col = ((lane >> 4) & 1) * 8;
    const int b_krow = (lane & 15);
    const int b_mcol = wn * 64 + ((lane >> 4) & 1) * 8;

    float acc[8][4];
    #pragma unroll
    for (int ni = 0; ni < 8; ni++)
        #pragma unroll
        for (int q = 0; q < 4; q++) acc[ni][q] = 0.0f;

    for (int l0 = 0; l0 < LL; l0 += 64) {
        if (l0) __syncthreads();

        #pragma unroll
        for (int p = 0; p < 4; p++) {
            const int row = xr + p * 16;      // c
            const size_t g = hoff + (size_t)row * LL + l0 + xc4;
            *(uint2*)&sXhi[row * XP + xc4] = *(const uint2*)&XH[g];
            *(uint2*)&sXlo[row * XP + xc4] = *(const uint2*)&XL[g];
        }
        #pragma unroll
        for (int p = 0; p < 4; p++) {
            const int row = prr + p * 16;     // l within chunk
            *(uint4*)&sP[row * PP + pc8] =
                *(const uint4*)&Ab[(size_t)(l0 + row) * LL + m0 + pc8];
        }
        __syncthreads();

        #pragma unroll
        for (int ks = 0; ks < 4; ks++) {
            const int kb = ks * 16;
            uint32_t ahi[4], alo[4], bp[8][2];

            {
                const uint32_t off = (uint32_t)(a_row * XP + kb + a_col) * 2;
                ldsm_x4(ahi, uXhi + off);
                ldsm_x4(alo, uXlo + off);
            }
            #pragma unroll
            for (int nq = 0; nq < 4; nq++) {
                const uint32_t off =
                    (uint32_t)((kb + b_krow) * PP + b_mcol + nq * 16) * 2;
                uint32_t th[4];
                ldsm_x4_t(th, uP + off);
                bp[nq * 2 + 0][0] = th[0]; bp[nq * 2 + 0][1] = th[1];
                bp[nq * 2 + 1][0] = th[2]; bp[nq * 2 + 1][1] = th[3];
            }

            #pragma unroll
            for (int ni = 0; ni < 8; ni++) {
                mma_bf16(acc[ni], ahi, bp[ni]);
                mma_bf16(acc[ni], alo, bp[ni]);
            }
        }
    }

    const int r = lane >> 2;
    const int g = lane & 3;
    const int c1 = wm * 16 + r;
    const int c2 = c1 + 8;

    #pragma unroll
    for (int ni = 0; ni < 8; ni++) {
        const int m = m0 + wn * 64 + ni * 8 + g * 2;
        const size_t i1 = hoff + (size_t)c1 * LL + m;
        const size_t i2 = hoff + (size_t)c2 * LL + m;
        *(uint32_t*)&OH[i1] = bf2_hi(acc[ni][0], acc[ni][1]);
        *(uint32_t*)&OL[i1] = bf2_hi(bf_res(acc[ni][0]), bf_res(acc[ni][1]));
        *(uint32_t*)&OH[i2] = bf2_hi(acc[ni][2], acc[ni][3]);
        *(uint32_t*)&OL[i2] = bf2_hi(bf_res(acc[ni][2]), bf_res(acc[ni][3]));
    }
}

// ---------------------------------------------------------------------------
extern "C" void kernel_launch(void* const* d_in, const int* in_sizes, int n_in,
                              void* d_out, int out_size)
{
    const float* x   = (const float*)d_in[0];
    const float* kw  = (const float*)d_in[1];
    const float* kb  = (const float*)d_in[2];
    const float* qw  = (const float*)d_in[3];
    const float* qb  = (const float*)d_in[4];
    const float* pw  = (const float*)d_in[5];
    const float* pb  = (const float*)d_in[6];
    const float* c1w = (const float*)d_in[7];
    const float* c1b = (const float*)d_in[8];
    const float* c2w = (const float*)d_in[9];
    const float* c2b = (const float*)d_in[10];
    float* out = (float*)d_out;

    __nv_bfloat16 *gXH,*gXL,*gKH,*gKL,*gQH,*gQL,*gAH,*gAL,*gYH,*gYL,*gTH,*gTL,*gS,*gWH,*gWL;
    float* gY;
    cudaGetSymbolAddress((void**)&gXH, g_XH); cudaGetSymbolAddress((void**)&gXL, g_XL);
    cudaGetSymbolAddress((void**)&gKH, g_KH); cudaGetSymbolAddress((void**)&gKL, g_KL);
    cudaGetSymbolAddress((void**)&gQH, g_QH); cudaGetSymbolAddress((void**)&gQL, g_QL);
    cudaGetSymbolAddress((void**)&gAH, g_AH); cudaGetSymbolAddress((void**)&gAL, g_AL);
    cudaGetSymbolAddress((void**)&gYH, g_YH); cudaGetSymbolAddress((void**)&gYL, g_YL);
    cudaGetSymbolAddress((void**)&gTH, g_TH); cudaGetSymbolAddress((void**)&gTL, g_TL);
    cudaGetSymbolAddress((void**)&gS,  g_S);
    cudaGetSymbolAddress((void**)&gWH, g_WH); cudaGetSymbolAddress((void**)&gWL, g_WL);
    cudaGetSymbolAddress((void**)&gY,  g_Y);

    static bool attr_done = false;
    if (!attr_done) {
        cudaFuncSetAttribute(scores_mma_kernel,
                             cudaFuncAttributeMaxDynamicSharedMemorySize, SCORES_SMEM);
        cudaFuncSetAttribute(av_mma_kernel,
                             cudaFuncAttributeMaxDynamicSharedMemorySize, AV_SMEM);
        cudaFuncSetAttribute(conv_mma_kernel<false, 0, 0>,
                             cudaFuncAttributeMaxDynamicSharedMemorySize, CONV_SMEM);
        cudaFuncSetAttribute(conv_mma_kernel<false, 1, 1>,
                             cudaFuncAttributeMaxDynamicSharedMemorySize, CONV_SMEM);
        cudaFuncSetAttribute(conv_mma_kernel<true, 0, 0>,
                             cudaFuncAttributeMaxDynamicSharedMemorySize, CONV_SMEM);
        cudaFuncSetAttribute(conv_mma_kernel<false, 2, 2>,
                             cudaFuncAttributeMaxDynamicSharedMemorySize, CONV_SMEM);
        attr_done = true;
    }

    // --- pre-split x and all weights into bf16 (hi, lo) pairs ---
    split_kernel<<<BCL / 4 / 256, 256>>>(x, gXH, gXL);
    split_kernel<<<WELEMS / 4 / 256, 256>>>(kw,  gWH + 0 * WELEMS, gWL + 0 * WELEMS);
    split_kernel<<<WELEMS / 4 / 256, 256>>>(qw,  gWH + 1 * WELEMS, gWL + 1 * WELEMS);
    split_kernel<<<WELEMS / 4 / 256, 256>>>(pw,  gWH + 2 * WELEMS, gWL + 2 * WELEMS);
    split_kernel<<<WELEMS / 4 / 256, 256>>>(c1w, gWH + 3 * WELEMS, gWL + 3 * WELEMS);
    split_kernel<<<WELEMS / 4 / 256, 256>>>(c2w, gWH + 4 * WELEMS, gWL + 4 * WELEMS);

    dim3 cgrid(LL / 128, CC / 128, BB);   // (16,8,2)

    // K and Q projections -> split outputs only
    conv_mma_kernel<false, 0, 0><<<cgrid, 256, CONV_SMEM>>>(
        gWH + 0 * WELEMS, gWL + 0 * WELEMS, kb, gXH, gXL,
        nullptr, gKH, gKL, nullptr, nullptr);
    conv_mma_kernel<false, 0, 0><<<cgrid, 256, CONV_SMEM>>>(
        gWH + 1 * WELEMS, gWL + 1 * WELEMS, qb, gXH, gXL,
        nullptr, gQH, gQL, nullptr, nullptr);

    // scores -> softmax -> AV
    scores_mma_kernel<<<dim3(LL / 128, LL / 128, NBH), 256, SCORES_SMEM>>>(
        gKH, gKL, gQH, gQL, gS);
    softmax_bf16_kernel<<<(unsigned)SROWS, 256>>>(gS);
    av_mma_kernel<<<dim3(LL / 128, NBH), 256, AV_SMEM>>>(gXH, gXL, gS, gAH, gAL);

    // y = pconv(AO) + x   (fp32 for residual + split for c1)
    conv_mma_kernel<false, 1, 1><<<cgrid, 256, CONV_SMEM>>>(
        gWH + 2 * WELEMS, gWL + 2 * WELEMS, pb, gAH, gAL,
        gY, gYH, gYL, x, nullptr);
    // t = relu(c1(y)) -> split only
    conv_mma_kernel<true, 0, 0><<<cgrid, 256, CONV_SMEM>>>(
        gWH + 3 * WELEMS, gWL + 3 * WELEMS, c1b, gYH, gYL,
        nullptr, gTH, gTL, nullptr, nullptr);
    // out = c2(t) + y + x  (fp32 only)
    conv_mma_kernel<false, 2, 2><<<cgrid, 256, CONV_SMEM>>>(
        gWH + 4 * WELEMS, gWL + 4 * WELEMS, c2b, gTH, gTL,
        out, nullptr, nullptr, gY, x);
}